// round 1
// baseline (speedup 1.0000x reference)
#include <cuda_runtime.h>
#include <math.h>

#define Nn 50000
#define Ee 400000

// output packing: out[N*4], nh[N*64], nc[N*64], eh[E*32], ec[E*32]
#define OUT_OFF 0
#define NH_OFF  (Nn*4)
#define NC_OFF  (NH_OFF + Nn*64)
#define EH_OFF  (NC_OFF + Nn*64)
#define EC_OFF  (EH_OFF + Ee*32)

// ---------------- scratch (device globals; no allocation allowed) ----------
__device__ float g_cnt[Nn];
__device__ float g_enc[Nn*32];
__device__ float g_xcat[Nn*96];
__device__ float g_xh[Nn*256];     // [n, head, 64]
__device__ float g_as[Nn*4];
__device__ float g_ad[Nn*4];
__device__ float g_m[Nn*4];
__device__ float g_den[Nn*4];
__device__ float g_araw[Ee*4];
__device__ float g_xgat[Nn*64];
__device__ float g_agg[Nn*32];
__device__ float g_P[Nn*64];
__device__ float g_Q[Nn*64];

__device__ __forceinline__ float sigf(float x){ return 1.f/(1.f+expf(-x)); }
__device__ __forceinline__ float leaky(float x){ return x > 0.f ? x : 0.2f*x; }
__device__ __forceinline__ void atomicMaxF(float* a, float v){
    if (v >= 0.f) atomicMax((int*)a, __float_as_int(v));
    else          atomicMin((unsigned int*)a, __float_as_uint(v));
}

// ---------------- init: zero the atomic accumulators -----------------------
__global__ void k_init(){
    int t = blockIdx.x*blockDim.x + threadIdx.x;
    int stride = gridDim.x*blockDim.x;
    for (int i=t; i<Nn; i+=stride) g_cnt[i] = 0.f;
    for (int i=t; i<Nn*32; i+=stride) g_enc[i] = 0.f;
    for (int i=t; i<Nn*32; i+=stride) g_agg[i] = 0.f;
}

// ---------------- K1: edge LSTM + scatter mean numerator -------------------
__global__ void k_edge_lstm(const float* __restrict__ ea, const int* __restrict__ ei,
                            const float* __restrict__ h0, const float* __restrict__ c0,
                            const float* __restrict__ Wih, const float* __restrict__ Whh,
                            const float* __restrict__ b, float* __restrict__ outp){
    __shared__ float sWhh[128*32];
    __shared__ float sWih[128*2];
    __shared__ float sb[128];
    for (int i=threadIdx.x; i<128*32; i+=blockDim.x) sWhh[i]=Whh[i];
    for (int i=threadIdx.x; i<256;    i+=blockDim.x) sWih[i]=Wih[i];
    for (int i=threadIdx.x; i<128;    i+=blockDim.x) sb[i]=b[i];
    __syncthreads();
    for (int e = blockIdx.x*blockDim.x + threadIdx.x; e < Ee; e += gridDim.x*blockDim.x){
        float x0 = ea[e*2], x1 = ea[e*2+1];
        float h[32];
        #pragma unroll
        for (int k=0;k<32;k++) h[k] = h0[e*32+k];
        int d = ei[Ee + e];
        #pragma unroll 2
        for (int j=0;j<32;j++){
            float gi = sb[j]    + x0*sWih[2*j]       + x1*sWih[2*j+1];
            float gf = sb[32+j] + x0*sWih[2*(32+j)]  + x1*sWih[2*(32+j)+1];
            float gg = sb[64+j] + x0*sWih[2*(64+j)]  + x1*sWih[2*(64+j)+1];
            float go = sb[96+j] + x0*sWih[2*(96+j)]  + x1*sWih[2*(96+j)+1];
            #pragma unroll
            for (int k=0;k<32;k++){
                float hk = h[k];
                gi += hk*sWhh[j*32+k];
                gf += hk*sWhh[(32+j)*32+k];
                gg += hk*sWhh[(64+j)*32+k];
                go += hk*sWhh[(96+j)*32+k];
            }
            float c  = c0[e*32+j];
            float c2 = sigf(gf)*c + sigf(gi)*tanhf(gg);
            float h2 = sigf(go)*tanhf(c2);
            outp[EH_OFF + e*32 + j] = h2;
            outp[EC_OFF + e*32 + j] = c2;
            atomicAdd(&g_enc[d*32 + j], h2);
        }
        atomicAdd(&g_cnt[d], 1.f);
    }
}

// ---------------- K2: node LSTM (warp per node, chunked Whh in smem) -------
__global__ void k_node_lstm(const float* __restrict__ x, const float* __restrict__ h0,
                            const float* __restrict__ c0, const float* __restrict__ Wih,
                            const float* __restrict__ Whh, const float* __restrict__ b,
                            float* __restrict__ outp){
    __shared__ float sW[256*17];
    __shared__ float sWih[256*5];
    __shared__ float sb[256];
    __shared__ float sh[16][64];
    __shared__ float sx[16][5];
    int warp = threadIdx.x>>5, lane = threadIdx.x&31;
    int node = blockIdx.x*16 + warp;
    for (int i=threadIdx.x; i<256*5; i+=blockDim.x) sWih[i]=Wih[i];
    for (int i=threadIdx.x; i<256;   i+=blockDim.x) sb[i]=b[i];
    if (node < Nn){
        sh[warp][lane]    = h0[node*64+lane];
        sh[warp][lane+32] = h0[node*64+lane+32];
        if (lane < 5) sx[warp][lane] = x[node*5+lane];
    }
    __syncthreads();
    float acc[8];
    #pragma unroll
    for (int g=0; g<4; g++)
        #pragma unroll
        for (int s=0; s<2; s++){
            int row = g*64 + lane + s*32;
            float a = sb[row];
            #pragma unroll
            for (int k=0;k<5;k++) a += sx[warp][k]*sWih[row*5+k];
            acc[g*2+s] = a;
        }
    for (int kc=0; kc<4; kc++){
        __syncthreads();
        for (int i=threadIdx.x; i<256*16; i+=blockDim.x){
            int r = i>>4, kk = i&15;
            sW[r*17+kk] = Whh[r*64 + kc*16 + kk];
        }
        __syncthreads();
        #pragma unroll
        for (int g=0; g<4; g++)
            #pragma unroll
            for (int s=0; s<2; s++){
                int row = g*64 + lane + s*32;
                float a = acc[g*2+s];
                #pragma unroll
                for (int kk=0; kk<16; kk++)
                    a += sh[warp][kc*16+kk]*sW[row*17+kk];
                acc[g*2+s] = a;
            }
    }
    if (node < Nn){
        #pragma unroll
        for (int s=0; s<2; s++){
            int j = lane + s*32;
            float c  = c0[node*64+j];
            float c2 = sigf(acc[2+s])*c + sigf(acc[0+s])*tanhf(acc[4+s]);
            float h2 = sigf(acc[6+s])*tanhf(c2);
            outp[NH_OFF + node*64 + j] = h2;
            outp[NC_OFF + node*64 + j] = c2;
            g_xcat[node*96 + j] = h2;
        }
    }
}

// ---------------- K3: edge_enc = sum / clip(cnt,1) -------------------------
__global__ void k_enc_div(){
    int t = blockIdx.x*blockDim.x + threadIdx.x;
    if (t >= Nn*32) return;
    int n = t>>5, j = t&31;
    g_xcat[n*96 + 64 + j] = g_enc[t] / fmaxf(g_cnt[n], 1.f);
}

// ---------------- K4: GAT projection xh = xcat @ gat_W.T -------------------
__global__ void k_gat_proj(const float* __restrict__ W){
    __shared__ float sW[256*33];
    __shared__ float sxc[16][96];
    int warp = threadIdx.x>>5, lane = threadIdx.x&31;
    int node = blockIdx.x*16 + warp;
    if (node < Nn){
        for (int k=lane; k<96; k+=32) sxc[warp][k] = g_xcat[node*96+k];
    }
    float acc[8];
    #pragma unroll
    for (int i=0;i<8;i++) acc[i]=0.f;
    for (int kc=0; kc<3; kc++){
        __syncthreads();
        for (int i=threadIdx.x; i<256*32; i+=blockDim.x){
            int r = i>>5, kk = i&31;
            sW[r*33+kk] = W[r*96 + kc*32 + kk];
        }
        __syncthreads();
        #pragma unroll
        for (int kk=0; kk<32; kk++){
            float v = sxc[warp][kc*32+kk];
            #pragma unroll
            for (int i=0;i<8;i++) acc[i] += v*sW[(lane+32*i)*33+kk];
        }
    }
    if (node < Nn){
        #pragma unroll
        for (int i=0;i<8;i++) g_xh[node*256 + lane + 32*i] = acc[i];
    }
}

// ---------------- K5: attention logits + m init (self loop) ----------------
__global__ void k_att(const float* __restrict__ att_s, const float* __restrict__ att_d){
    __shared__ float ss[256], sd[256];
    for (int i=threadIdx.x; i<256; i+=blockDim.x){ ss[i]=att_s[i]; sd[i]=att_d[i]; }
    __syncthreads();
    int t = blockIdx.x*blockDim.x + threadIdx.x;
    if (t >= Nn*4) return;
    int n = t>>2, h = t&3;
    const float* xh = &g_xh[n*256 + h*64];
    float as=0.f, ad=0.f;
    #pragma unroll
    for (int d=0; d<64; d++){ float v=xh[d]; as += v*ss[h*64+d]; ad += v*sd[h*64+d]; }
    g_as[t]=as; g_ad[t]=ad;
    g_m[t] = leaky(as+ad);          // self-loop seeds the segment max
}

// ---------------- K6: edge alpha raw + segment max --------------------------
__global__ void k_edge_max(const int* __restrict__ ei){
    int t = blockIdx.x*blockDim.x + threadIdx.x;
    if (t >= Ee*4) return;
    int e = t>>2, h = t&3;
    int s = ei[e], d = ei[Ee+e];
    float ar = leaky(g_as[s*4+h] + g_ad[d*4+h]);
    g_araw[t] = ar;
    atomicMaxF(&g_m[d*4+h], ar);
}

// ---------------- K7b: denom init with self-loop term ----------------------
__global__ void k_den_init(){
    int t = blockIdx.x*blockDim.x + threadIdx.x;
    if (t >= Nn*4) return;
    float self = leaky(g_as[t] + g_ad[t]);
    g_den[t] = expf(self - g_m[t]);
}

// ---------------- K7: edge exp + denom accumulation -------------------------
__global__ void k_edge_exp(const int* __restrict__ ei){
    int t = blockIdx.x*blockDim.x + threadIdx.x;
    if (t >= Ee*4) return;
    int e = t>>2, h = t&3;
    int d = ei[Ee+e];
    float w = expf(g_araw[t] - g_m[d*4+h]);
    g_araw[t] = w;
    atomicAdd(&g_den[d*4+h], w);
}

// ---------------- K8b: self-loop message (non-atomic init) -----------------
__global__ void k_self_msg(){
    int t = blockIdx.x*blockDim.x + threadIdx.x;
    if (t >= Nn*64) return;
    int n = t>>6, dd = t&63;
    float acc = 0.f;
    #pragma unroll
    for (int h=0; h<4; h++){
        float w = expf(leaky(g_as[n*4+h]+g_ad[n*4+h]) - g_m[n*4+h]) / g_den[n*4+h];
        acc += w * g_xh[n*256 + h*64 + dd];
    }
    g_xgat[t] = acc;
}

// ---------------- K8: edge messages (warp per edge, atomic) ----------------
__global__ void k_msg(const int* __restrict__ ei){
    int warp = threadIdx.x>>5, lane = threadIdx.x&31;
    int e = blockIdx.x*8 + warp;
    if (e >= Ee) return;
    int s = ei[e], d = ei[Ee+e];
    float w0 = g_araw[e*4+0]/g_den[d*4+0];
    float w1 = g_araw[e*4+1]/g_den[d*4+1];
    float w2 = g_araw[e*4+2]/g_den[d*4+2];
    float w3 = g_araw[e*4+3]/g_den[d*4+3];
    const float* xs = &g_xh[s*256];
    float a0 = w0*xs[lane]    + w1*xs[64+lane]  + w2*xs[128+lane] + w3*xs[192+lane];
    float a1 = w0*xs[32+lane] + w1*xs[96+lane]  + w2*xs[160+lane] + w3*xs[224+lane];
    atomicAdd(&g_xgat[d*64 + lane],      a0);
    atomicAdd(&g_xgat[d*64 + 32 + lane], a1);
}

// ---------------- K9: finalize x_gat (mean heads + bias) -------------------
__global__ void k_xgat_fin(const float* __restrict__ bias){
    int t = blockIdx.x*blockDim.x + threadIdx.x;
    if (t >= Nn*64) return;
    g_xgat[t] = g_xgat[t]*0.25f + bias[t&63];
}

// ---------------- K10a: edge-MLP factorization: P = W1a@xg + b1, Q = W1b@xg -
__global__ void k_pq(const float* __restrict__ W1, const float* __restrict__ b1){
    __shared__ float sWa[64*64];   // transposed [k][j]
    __shared__ float sWb[64*64];
    __shared__ float sxg[8][64];
    __shared__ float sb1[64];
    int warp = threadIdx.x>>5, lane = threadIdx.x&31;
    for (int i=threadIdx.x; i<4096; i+=blockDim.x){
        int j = i>>6, k = i&63;
        sWa[k*64+j] = W1[j*130 + k];
        sWb[k*64+j] = W1[j*130 + 64 + k];
    }
    for (int i=threadIdx.x; i<64; i+=blockDim.x) sb1[i]=b1[i];
    __syncthreads();
    for (int n0 = blockIdx.x*8; n0 < Nn; n0 += gridDim.x*8){
        int n = n0 + warp;
        if (n < Nn){
            sxg[warp][lane]    = g_xgat[n*64+lane];
            sxg[warp][lane+32] = g_xgat[n*64+32+lane];
        }
        __syncwarp();
        if (n < Nn){
            float p0=sb1[lane], p1=sb1[lane+32], q0=0.f, q1=0.f;
            #pragma unroll
            for (int k=0;k<64;k++){
                float v = sxg[warp][k];
                p0 += v*sWa[k*64+lane]; p1 += v*sWa[k*64+32+lane];
                q0 += v*sWb[k*64+lane]; q1 += v*sWb[k*64+32+lane];
            }
            g_P[n*64+lane]=p0; g_P[n*64+32+lane]=p1;
            g_Q[n*64+lane]=q0; g_Q[n*64+32+lane]=q1;
        }
        __syncwarp();
    }
}

// ---------------- K10b: per-edge MLP (factored layer1) + agg scatter -------
__global__ void k_edge_mlp(const int* __restrict__ ei, const float* __restrict__ ea,
                           const float* __restrict__ W1, const float* __restrict__ W2,
                           const float* __restrict__ b2){
    __shared__ float sW2[64*32];   // [j][l]
    __shared__ float sw128[64], sw129[64], sb2[32];
    __shared__ float sh1[8][64];
    int warp = threadIdx.x>>5, lane = threadIdx.x&31;
    for (int i=threadIdx.x; i<2048; i+=blockDim.x){
        int l = i>>6, j = i&63;
        sW2[j*32+l] = W2[i];
    }
    for (int i=threadIdx.x; i<64; i+=blockDim.x){
        sw128[i]=W1[i*130+128]; sw129[i]=W1[i*130+129];
    }
    if (threadIdx.x < 32) sb2[threadIdx.x]=b2[threadIdx.x];
    __syncthreads();
    int e = blockIdx.x*8 + warp;
    if (e >= Ee) return;
    int s = ei[e], d = ei[Ee+e];
    float e0 = ea[e*2], e1 = ea[e*2+1];
    float h0 = fmaxf(g_P[s*64+lane]   + g_Q[d*64+lane]   + e0*sw128[lane]   + e1*sw129[lane],   0.f);
    float h1 = fmaxf(g_P[s*64+32+lane]+ g_Q[d*64+32+lane]+ e0*sw128[32+lane]+ e1*sw129[32+lane],0.f);
    sh1[warp][lane]=h0; sh1[warp][lane+32]=h1;
    __syncwarp();
    float acc = sb2[lane];
    #pragma unroll
    for (int j=0;j<64;j++) acc += sh1[warp][j]*sW2[j*32+lane];
    atomicAdd(&g_agg[d*32+lane], acc);
}

// ---------------- K11: node MLP -> out --------------------------------------
__global__ void k_node_mlp(const float* __restrict__ W1, const float* __restrict__ b1,
                           const float* __restrict__ W2, const float* __restrict__ b2,
                           float* __restrict__ outp){
    __shared__ float sW1[96*64];   // [k][j]
    __shared__ float sW2[4*64];
    __shared__ float sb1[64];
    __shared__ float snin[8][96];
    int warp = threadIdx.x>>5, lane = threadIdx.x&31;
    for (int i=threadIdx.x; i<96*64; i+=blockDim.x){
        int j = i/96, k = i%96;
        sW1[k*64+j] = W1[i];
    }
    for (int i=threadIdx.x; i<256; i+=blockDim.x) sW2[i]=W2[i];
    for (int i=threadIdx.x; i<64;  i+=blockDim.x) sb1[i]=b1[i];
    __syncthreads();
    for (int n0 = blockIdx.x*8; n0 < Nn; n0 += gridDim.x*8){
        int n = n0 + warp;
        if (n < Nn){
            snin[warp][lane]    = g_xgat[n*64+lane];
            snin[warp][32+lane] = g_xgat[n*64+32+lane];
            float inv = 1.f/fmaxf(g_cnt[n],1.f);
            snin[warp][64+lane] = g_agg[n*32+lane]*inv;
        }
        __syncwarp();
        if (n < Nn){
            float a0=sb1[lane], a1=sb1[lane+32];
            #pragma unroll
            for (int k=0;k<96;k++){
                float v = snin[warp][k];
                a0 += v*sW1[k*64+lane];
                a1 += v*sW1[k*64+32+lane];
            }
            a0 = fmaxf(a0,0.f); a1 = fmaxf(a1,0.f);
            float p0 = a0*sW2[0*64+lane] + a1*sW2[0*64+32+lane];
            float p1 = a0*sW2[1*64+lane] + a1*sW2[1*64+32+lane];
            float p2 = a0*sW2[2*64+lane] + a1*sW2[2*64+32+lane];
            float p3 = a0*sW2[3*64+lane] + a1*sW2[3*64+32+lane];
            #pragma unroll
            for (int off=16; off; off>>=1){
                p0 += __shfl_down_sync(0xffffffff, p0, off);
                p1 += __shfl_down_sync(0xffffffff, p1, off);
                p2 += __shfl_down_sync(0xffffffff, p2, off);
                p3 += __shfl_down_sync(0xffffffff, p3, off);
            }
            if (lane == 0){
                outp[OUT_OFF + n*4+0] = p0 + b2[0];
                outp[OUT_OFF + n*4+1] = p1 + b2[1];
                outp[OUT_OFF + n*4+2] = p2 + b2[2];
                outp[OUT_OFF + n*4+3] = p3 + b2[3];
            }
        }
        __syncwarp();
    }
}

extern "C" void kernel_launch(void* const* d_in, const int* in_sizes, int n_in,
                              void* d_out, int out_size){
    (void)in_sizes; (void)n_in; (void)out_size;
    const float* x    = (const float*)d_in[0];
    const int*   ei   = (const int*)  d_in[1];
    const float* ea   = (const float*)d_in[2];
    const float* hnh  = (const float*)d_in[3];
    const float* hnc  = (const float*)d_in[4];
    const float* heh  = (const float*)d_in[5];
    const float* hec  = (const float*)d_in[6];
    const float* nWih = (const float*)d_in[7];
    const float* nWhh = (const float*)d_in[8];
    const float* nb   = (const float*)d_in[9];
    const float* eWih = (const float*)d_in[10];
    const float* eWhh = (const float*)d_in[11];
    const float* eb   = (const float*)d_in[12];
    const float* gatW = (const float*)d_in[13];
    const float* attS = (const float*)d_in[14];
    const float* attD = (const float*)d_in[15];
    const float* gatB = (const float*)d_in[16];
    const float* emW1 = (const float*)d_in[17];
    const float* emb1 = (const float*)d_in[18];
    const float* emW2 = (const float*)d_in[19];
    const float* emb2 = (const float*)d_in[20];
    const float* nmW1 = (const float*)d_in[21];
    const float* nmb1 = (const float*)d_in[22];
    const float* nmW2 = (const float*)d_in[23];
    const float* nmb2 = (const float*)d_in[24];
    float* out = (float*)d_out;

    k_init<<<1024, 256>>>();
    k_edge_lstm<<<1184, 256>>>(ea, ei, heh, hec, eWih, eWhh, eb, out);
    k_node_lstm<<<(Nn+15)/16, 512>>>(x, hnh, hnc, nWih, nWhh, nb, out);
    k_enc_div<<<(Nn*32+255)/256, 256>>>();
    k_gat_proj<<<(Nn+15)/16, 512>>>(gatW);
    k_att<<<(Nn*4+255)/256, 256>>>(attS, attD);
    k_edge_max<<<(Ee*4+255)/256, 256>>>(ei);
    k_den_init<<<(Nn*4+255)/256, 256>>>();
    k_edge_exp<<<(Ee*4+255)/256, 256>>>(ei);
    k_self_msg<<<(Nn*64+255)/256, 256>>>();
    k_msg<<<(Ee+7)/8, 256>>>(ei);
    k_xgat_fin<<<(Nn*64+255)/256, 256>>>(gatB);
    k_pq<<<740, 256>>>(emW1, emb1);
    k_edge_mlp<<<(Ee+7)/8, 256>>>(ei, ea, emW1, emW2, emb2);
    k_node_mlp<<<740, 256>>>(nmW1, nmb1, nmW2, nmb2, out);
}

// round 2
// speedup vs baseline: 1.7273x; 1.7273x over previous
#include <cuda_runtime.h>
#include <math.h>

#define Nn 50000
#define Ee 400000

// output packing: out[N*4], nh[N*64], nc[N*64], eh[E*32], ec[E*32]
#define OUT_OFF 0
#define NH_OFF  (Nn*4)
#define NC_OFF  (NH_OFF + Nn*64)
#define EH_OFF  (NC_OFF + Nn*64)
#define EC_OFF  (EH_OFF + Ee*32)

// ---------------- scratch (device globals; no allocation allowed) ----------
__device__ float g_cnt[Nn];
__device__ float g_enc[Nn*32];
__device__ float g_xcat[Nn*96];
__device__ float g_xh[Nn*256];     // [n, head, 64]
__device__ float g_as[Nn*4];
__device__ float g_ad[Nn*4];
__device__ float g_m[Nn*4];
__device__ float g_den[Nn*4];
__device__ float g_araw[Ee*4];
__device__ float g_xgat[Nn*64];
__device__ float g_agg[Nn*32];
__device__ float g_P[Nn*64];
__device__ float g_Q[Nn*64];

__device__ __forceinline__ float fsig(float x){ return __fdividef(1.f, 1.f+__expf(-x)); }
__device__ __forceinline__ float ftanhf(float x){ return __fdividef(2.f, 1.f+__expf(-2.f*x)) - 1.f; }
__device__ __forceinline__ float leaky(float x){ return x > 0.f ? x : 0.2f*x; }
__device__ __forceinline__ void atomicMaxF(float* a, float v){
    if (v >= 0.f) atomicMax((int*)a, __float_as_int(v));
    else          atomicMin((unsigned int*)a, __float_as_uint(v));
}

// ---------------- init: zero the atomic accumulators -----------------------
__global__ void k_init(){
    int t = blockIdx.x*blockDim.x + threadIdx.x;
    int stride = gridDim.x*blockDim.x;
    for (int i=t; i<Nn; i+=stride) g_cnt[i] = 0.f;
    for (int i=t; i<Nn*32; i+=stride) g_enc[i] = 0.f;
    for (int i=t; i<Nn*32; i+=stride) g_agg[i] = 0.f;
}

// ---------------- K1: edge LSTM (thread/edge, float4 broadcast LDS) --------
__global__ void __launch_bounds__(256) k_edge_lstm(
        const float* __restrict__ ea, const int* __restrict__ ei,
        const float* __restrict__ h0, const float* __restrict__ c0,
        const float* __restrict__ Wih, const float* __restrict__ Whh,
        const float* __restrict__ b, float* __restrict__ outp){
    __shared__ float4 sW4[128*8];    // Whh [row][k/4]
    __shared__ float sWih[256];
    __shared__ float sb[128];
    {
        float* sw = (float*)sW4;
        for (int i=threadIdx.x; i<4096; i+=256) sw[i] = Whh[i];
        for (int i=threadIdx.x; i<256;  i+=256) sWih[i] = Wih[i];
        for (int i=threadIdx.x; i<128;  i+=256) sb[i] = b[i];
    }
    __syncthreads();
    int e = blockIdx.x*256 + threadIdx.x;
    if (e >= Ee) return;

    float2 xv = ((const float2*)ea)[e];
    float4 h4[8];
    const float4* h0v = (const float4*)h0;
    #pragma unroll
    for (int i=0;i<8;i++) h4[i] = h0v[e*8+i];
    int d = ei[Ee + e];
    const float4* c0v = (const float4*)c0;
    float4* outv = (float4*)outp;

    #pragma unroll 1
    for (int j0=0;j0<32;j0+=4){
        float acc[4][4];       // [jj][gate]
        #pragma unroll
        for (int g=0; g<4; g++)
            #pragma unroll
            for (int jj=0; jj<4; jj++){
                int row = g*32 + j0 + jj;
                acc[jj][g] = sb[row] + xv.x*sWih[2*row] + xv.y*sWih[2*row+1];
            }
        #pragma unroll
        for (int k4=0; k4<8; k4++){
            float4 hk = h4[k4];
            #pragma unroll
            for (int g=0; g<4; g++)
                #pragma unroll
                for (int jj=0; jj<4; jj++){
                    float4 w = sW4[(g*32 + j0 + jj)*8 + k4];
                    acc[jj][g] += hk.x*w.x + hk.y*w.y + hk.z*w.z + hk.w*w.w;
                }
        }
        float4 cv = c0v[e*8 + (j0>>2)];
        float cc[4] = {cv.x, cv.y, cv.z, cv.w};
        float h2a[4], c2a[4];
        #pragma unroll
        for (int jj=0; jj<4; jj++){
            float c2 = fsig(acc[jj][1])*cc[jj] + fsig(acc[jj][0])*ftanhf(acc[jj][2]);
            float h2 = fsig(acc[jj][3])*ftanhf(c2);
            h2a[jj]=h2; c2a[jj]=c2;
            atomicAdd(&g_enc[d*32 + j0 + jj], h2);
        }
        outv[(EH_OFF + e*32 + j0)>>2] = make_float4(h2a[0],h2a[1],h2a[2],h2a[3]);
        outv[(EC_OFF + e*32 + j0)>>2] = make_float4(c2a[0],c2a[1],c2a[2],c2a[3]);
    }
    atomicAdd(&g_cnt[d], 1.f);
}

// ---------------- K2: node LSTM (thread/node, Whh fully in dyn smem) -------
__global__ void __launch_bounds__(256) k_node_lstm(
        const float* __restrict__ x, const float* __restrict__ h0,
        const float* __restrict__ c0, const float* __restrict__ Wih,
        const float* __restrict__ Whh, const float* __restrict__ b,
        float* __restrict__ outp){
    extern __shared__ float dyn[];
    float4* sW4 = (float4*)dyn;             // 256*16 float4 (Whh [row][k/4])
    float*  sWih = dyn + 256*64;            // 256*5
    float*  sb   = sWih + 256*5;            // 256
    {
        float* sw = dyn;
        for (int i=threadIdx.x; i<256*64; i+=256) sw[i] = Whh[i];
        for (int i=threadIdx.x; i<256*5;  i+=256) sWih[i] = Wih[i];
        for (int i=threadIdx.x; i<256;    i+=256) sb[i] = b[i];
    }
    __syncthreads();
    int node = blockIdx.x*256 + threadIdx.x;
    if (node >= Nn) return;

    float xr[5];
    #pragma unroll
    for (int k=0;k<5;k++) xr[k] = x[node*5+k];
    float4 h4[16];
    const float4* h0v = (const float4*)h0;
    #pragma unroll
    for (int i=0;i<16;i++) h4[i] = h0v[node*16+i];
    const float4* c0v = (const float4*)c0;
    float4* outv = (float4*)outp;

    #pragma unroll 1
    for (int j0=0;j0<64;j0+=4){
        float acc[4][4];
        #pragma unroll
        for (int g=0; g<4; g++)
            #pragma unroll
            for (int jj=0; jj<4; jj++){
                int row = g*64 + j0 + jj;
                float a = sb[row];
                #pragma unroll
                for (int k=0;k<5;k++) a += xr[k]*sWih[row*5+k];
                acc[jj][g] = a;
            }
        #pragma unroll
        for (int k4=0; k4<16; k4++){
            float4 hk = h4[k4];
            #pragma unroll
            for (int g=0; g<4; g++)
                #pragma unroll
                for (int jj=0; jj<4; jj++){
                    float4 w = sW4[(g*64 + j0 + jj)*16 + k4];
                    acc[jj][g] += hk.x*w.x + hk.y*w.y + hk.z*w.z + hk.w*w.w;
                }
        }
        float4 cv = c0v[node*16 + (j0>>2)];
        float cc[4] = {cv.x, cv.y, cv.z, cv.w};
        float h2a[4], c2a[4];
        #pragma unroll
        for (int jj=0; jj<4; jj++){
            float c2 = fsig(acc[jj][1])*cc[jj] + fsig(acc[jj][0])*ftanhf(acc[jj][2]);
            float h2 = fsig(acc[jj][3])*ftanhf(c2);
            h2a[jj]=h2; c2a[jj]=c2;
        }
        float4 h2v = make_float4(h2a[0],h2a[1],h2a[2],h2a[3]);
        outv[(NH_OFF + node*64 + j0)>>2] = h2v;
        outv[(NC_OFF + node*64 + j0)>>2] = make_float4(c2a[0],c2a[1],c2a[2],c2a[3]);
        ((float4*)g_xcat)[(node*96 + j0)>>2] = h2v;
    }
}

// ---------------- K3: edge_enc = sum / clip(cnt,1) -------------------------
__global__ void k_enc_div(){
    int t = blockIdx.x*blockDim.x + threadIdx.x;
    if (t >= Nn*32) return;
    int n = t>>5, j = t&31;
    g_xcat[n*96 + 64 + j] = __fdividef(g_enc[t], fmaxf(g_cnt[n], 1.f));
}

// ---------------- K4: GAT projection (persistent, W in dyn smem) -----------
__global__ void __launch_bounds__(512) k_gat_proj(const float* __restrict__ W){
    extern __shared__ float dyn[];
    float* sW  = dyn;               // [256 rows][96 kk] pad stride 100
    float* sxc = dyn + 25600;       // [16 warps][96]
    for (int i=threadIdx.x; i<24576; i+=512){
        int r = i/96, k = i - r*96;
        sW[r*100 + k] = W[i];
    }
    __syncthreads();
    int warp = threadIdx.x>>5, lane = threadIdx.x&31;
    for (int base = blockIdx.x*16; base < Nn; base += gridDim.x*16){
        int node = base + warp;
        if (node < Nn){
            float* xc = &sxc[warp*96];
            xc[lane]    = g_xcat[node*96 + lane];
            xc[lane+32] = g_xcat[node*96 + 32 + lane];
            xc[lane+64] = g_xcat[node*96 + 64 + lane];
        }
        __syncwarp();
        if (node < Nn){
            float acc[8];
            #pragma unroll
            for (int i=0;i<8;i++) acc[i]=0.f;
            #pragma unroll 4
            for (int kk0=0; kk0<96; kk0+=4){
                float4 xv = *(const float4*)&sxc[warp*96 + kk0];
                #pragma unroll
                for (int i=0;i<8;i++){
                    float4 w = *(const float4*)&sW[(lane + 32*i)*100 + kk0];
                    acc[i] += xv.x*w.x + xv.y*w.y + xv.z*w.z + xv.w*w.w;
                }
            }
            #pragma unroll
            for (int i=0;i<8;i++) g_xh[node*256 + lane + 32*i] = acc[i];
        }
        __syncwarp();
    }
}

// ---------------- K5: attention logits + m init (self loop) ----------------
__global__ void k_att(const float* __restrict__ att_s, const float* __restrict__ att_d){
    __shared__ float ss[256], sd[256];
    for (int i=threadIdx.x; i<256; i+=blockDim.x){ ss[i]=att_s[i]; sd[i]=att_d[i]; }
    __syncthreads();
    int t = blockIdx.x*blockDim.x + threadIdx.x;
    if (t >= Nn*4) return;
    int n = t>>2, h = t&3;
    const float4* xh4 = (const float4*)(g_xh + n*256 + h*64);
    float as=0.f, ad=0.f;
    #pragma unroll
    for (int d4=0; d4<16; d4++){
        float4 xv = xh4[d4];
        float4 sv = *(const float4*)&ss[h*64 + d4*4];
        float4 dv = *(const float4*)&sd[h*64 + d4*4];
        as += xv.x*sv.x + xv.y*sv.y + xv.z*sv.z + xv.w*sv.w;
        ad += xv.x*dv.x + xv.y*dv.y + xv.z*dv.z + xv.w*dv.w;
    }
    g_as[t]=as; g_ad[t]=ad;
    g_m[t] = leaky(as+ad);          // self-loop seeds the segment max
}

// ---------------- K6: edge alpha raw + segment max --------------------------
__global__ void k_edge_max(const int* __restrict__ ei){
    int t = blockIdx.x*blockDim.x + threadIdx.x;
    if (t >= Ee*4) return;
    int e = t>>2, h = t&3;
    int s = ei[e], d = ei[Ee+e];
    float ar = leaky(g_as[s*4+h] + g_ad[d*4+h]);
    g_araw[t] = ar;
    atomicMaxF(&g_m[d*4+h], ar);
}

// ---------------- K7b: denom init with self-loop term ----------------------
__global__ void k_den_init(){
    int t = blockIdx.x*blockDim.x + threadIdx.x;
    if (t >= Nn*4) return;
    float self = leaky(g_as[t] + g_ad[t]);
    g_den[t] = __expf(self - g_m[t]);
}

// ---------------- K7: edge exp + denom accumulation -------------------------
__global__ void k_edge_exp(const int* __restrict__ ei){
    int t = blockIdx.x*blockDim.x + threadIdx.x;
    if (t >= Ee*4) return;
    int e = t>>2, h = t&3;
    int d = ei[Ee+e];
    float w = __expf(g_araw[t] - g_m[d*4+h]);
    g_araw[t] = w;
    atomicAdd(&g_den[d*4+h], w);
}

// ---------------- K8b: self-loop message (non-atomic init) -----------------
__global__ void k_self_msg(){
    int t = blockIdx.x*blockDim.x + threadIdx.x;
    if (t >= Nn*64) return;
    int n = t>>6, dd = t&63;
    float acc = 0.f;
    #pragma unroll
    for (int h=0; h<4; h++){
        float w = __fdividef(__expf(leaky(g_as[n*4+h]+g_ad[n*4+h]) - g_m[n*4+h]), g_den[n*4+h]);
        acc += w * g_xh[n*256 + h*64 + dd];
    }
    g_xgat[t] = acc;
}

// ---------------- K8: edge messages (warp per edge, atomic) ----------------
__global__ void k_msg(const int* __restrict__ ei){
    int warp = threadIdx.x>>5, lane = threadIdx.x&31;
    int e = blockIdx.x*8 + warp;
    if (e >= Ee) return;
    int s = ei[e], d = ei[Ee+e];
    float4 ar = *(const float4*)&g_araw[e*4];
    float4 dn = *(const float4*)&g_den[d*4];
    float w0 = __fdividef(ar.x, dn.x);
    float w1 = __fdividef(ar.y, dn.y);
    float w2 = __fdividef(ar.z, dn.z);
    float w3 = __fdividef(ar.w, dn.w);
    const float* xs = &g_xh[s*256];
    float a0 = w0*xs[lane]    + w1*xs[64+lane]  + w2*xs[128+lane] + w3*xs[192+lane];
    float a1 = w0*xs[32+lane] + w1*xs[96+lane]  + w2*xs[160+lane] + w3*xs[224+lane];
    atomicAdd(&g_xgat[d*64 + lane],      a0);
    atomicAdd(&g_xgat[d*64 + 32 + lane], a1);
}

// ---------------- K9: finalize x_gat (mean heads + bias) -------------------
__global__ void k_xgat_fin(const float* __restrict__ bias){
    int t = blockIdx.x*blockDim.x + threadIdx.x;
    if (t >= Nn*64) return;
    g_xgat[t] = g_xgat[t]*0.25f + bias[t&63];
}

// ---------------- K10a: P = W1a@xg + b1, Q = W1b@xg (persistent) -----------
__global__ void __launch_bounds__(512) k_pq(const float* __restrict__ W1, const float* __restrict__ b1){
    __shared__ float sW[128*68];     // rows 0..63: W1a[j][k]; rows 64..127: W1b[j][k]; pad 68
    __shared__ float sxg[16][64];
    __shared__ float sb1[64];
    for (int i=threadIdx.x; i<8192; i+=512){
        int r = i>>6, k = i&63;
        sW[r*68 + k] = (r < 64) ? W1[r*130 + k] : W1[(r-64)*130 + 64 + k];
    }
    for (int i=threadIdx.x; i<64; i+=512) sb1[i]=b1[i];
    __syncthreads();
    int warp = threadIdx.x>>5, lane = threadIdx.x&31;
    for (int base = blockIdx.x*16; base < Nn; base += gridDim.x*16){
        int n = base + warp;
        if (n < Nn){
            sxg[warp][lane]    = g_xgat[n*64+lane];
            sxg[warp][lane+32] = g_xgat[n*64+32+lane];
        }
        __syncwarp();
        if (n < Nn){
            float acc[4];     // rows lane+32*i : i=0,1 -> P ; i=2,3 -> Q
            acc[0]=sb1[lane]; acc[1]=sb1[lane+32]; acc[2]=0.f; acc[3]=0.f;
            #pragma unroll 4
            for (int k0=0;k0<64;k0+=4){
                float4 xv = *(const float4*)&sxg[warp][k0];
                #pragma unroll
                for (int i=0;i<4;i++){
                    float4 w = *(const float4*)&sW[(lane + 32*i)*68 + k0];
                    acc[i] += xv.x*w.x + xv.y*w.y + xv.z*w.z + xv.w*w.w;
                }
            }
            g_P[n*64+lane]=acc[0]; g_P[n*64+32+lane]=acc[1];
            g_Q[n*64+lane]=acc[2]; g_Q[n*64+32+lane]=acc[3];
        }
        __syncwarp();
    }
}

// ---------------- K10b: per-edge MLP (persistent) + agg scatter ------------
__global__ void __launch_bounds__(256) k_edge_mlp(
        const int* __restrict__ ei, const float* __restrict__ ea,
        const float* __restrict__ W1, const float* __restrict__ W2,
        const float* __restrict__ b2){
    __shared__ float sW2[32*68];   // [l][j] pad 68
    __shared__ float sw128[64], sw129[64], sb2[32];
    __shared__ float sh1[8][64];
    for (int i=threadIdx.x; i<2048; i+=256){
        int l = i>>6, j = i&63;
        sW2[l*68+j] = W2[l*64+j];
    }
    for (int i=threadIdx.x; i<64; i+=256){
        sw128[i]=W1[i*130+128]; sw129[i]=W1[i*130+129];
    }
    if (threadIdx.x < 32) sb2[threadIdx.x]=b2[threadIdx.x];
    __syncthreads();
    int warp = threadIdx.x>>5, lane = threadIdx.x&31;
    for (int e = blockIdx.x*8 + warp; e < Ee; e += gridDim.x*8){
        int s = ei[e], d = ei[Ee+e];
        float2 ev = ((const float2*)ea)[e];
        float h0 = fmaxf(g_P[s*64+lane]    + g_Q[d*64+lane]    + ev.x*sw128[lane]    + ev.y*sw129[lane],    0.f);
        float h1 = fmaxf(g_P[s*64+32+lane] + g_Q[d*64+32+lane] + ev.x*sw128[32+lane] + ev.y*sw129[32+lane], 0.f);
        sh1[warp][lane]=h0; sh1[warp][lane+32]=h1;
        __syncwarp();
        float acc = sb2[lane];
        #pragma unroll
        for (int j0=0;j0<64;j0+=4){
            float4 hv = *(const float4*)&sh1[warp][j0];
            float4 w  = *(const float4*)&sW2[lane*68 + j0];
            acc += hv.x*w.x + hv.y*w.y + hv.z*w.z + hv.w*w.w;
        }
        atomicAdd(&g_agg[d*32+lane], acc);
        __syncwarp();
    }
}

// ---------------- K11: node MLP -> out (persistent) -------------------------
__global__ void __launch_bounds__(256) k_node_mlp(
        const float* __restrict__ W1, const float* __restrict__ b1,
        const float* __restrict__ W2, const float* __restrict__ b2,
        float* __restrict__ outp){
    __shared__ float sW1[64*100];   // [row j][k] pad 100
    __shared__ float sW2[4*64];
    __shared__ float sb1[64];
    __shared__ float snin[8][96];
    for (int i=threadIdx.x; i<6144; i+=256){
        int r = i/96, k = i - r*96;
        sW1[r*100 + k] = W1[i];
    }
    for (int i=threadIdx.x; i<256; i+=256) sW2[i]=W2[i];
    for (int i=threadIdx.x; i<64;  i+=256) sb1[i]=b1[i];
    __syncthreads();
    int warp = threadIdx.x>>5, lane = threadIdx.x&31;
    for (int base = blockIdx.x*8; base < Nn; base += gridDim.x*8){
        int n = base + warp;
        if (n < Nn){
            snin[warp][lane]    = g_xgat[n*64+lane];
            snin[warp][32+lane] = g_xgat[n*64+32+lane];
            float inv = __fdividef(1.f, fmaxf(g_cnt[n],1.f));
            snin[warp][64+lane] = g_agg[n*32+lane]*inv;
        }
        __syncwarp();
        if (n < Nn){
            float a0=sb1[lane], a1=sb1[lane+32];
            #pragma unroll 4
            for (int k0=0;k0<96;k0+=4){
                float4 xv = *(const float4*)&snin[warp][k0];
                float4 w0 = *(const float4*)&sW1[lane*100 + k0];
                float4 w1 = *(const float4*)&sW1[(lane+32)*100 + k0];
                a0 += xv.x*w0.x + xv.y*w0.y + xv.z*w0.z + xv.w*w0.w;
                a1 += xv.x*w1.x + xv.y*w1.y + xv.z*w1.z + xv.w*w1.w;
            }
            a0 = fmaxf(a0,0.f); a1 = fmaxf(a1,0.f);
            float p0 = a0*sW2[0*64+lane] + a1*sW2[0*64+32+lane];
            float p1 = a0*sW2[1*64+lane] + a1*sW2[1*64+32+lane];
            float p2 = a0*sW2[2*64+lane] + a1*sW2[2*64+32+lane];
            float p3 = a0*sW2[3*64+lane] + a1*sW2[3*64+32+lane];
            #pragma unroll
            for (int off=16; off; off>>=1){
                p0 += __shfl_down_sync(0xffffffff, p0, off);
                p1 += __shfl_down_sync(0xffffffff, p1, off);
                p2 += __shfl_down_sync(0xffffffff, p2, off);
                p3 += __shfl_down_sync(0xffffffff, p3, off);
            }
            if (lane == 0){
                outp[OUT_OFF + n*4+0] = p0 + b2[0];
                outp[OUT_OFF + n*4+1] = p1 + b2[1];
                outp[OUT_OFF + n*4+2] = p2 + b2[2];
                outp[OUT_OFF + n*4+3] = p3 + b2[3];
            }
        }
        __syncwarp();
    }
}

extern "C" void kernel_launch(void* const* d_in, const int* in_sizes, int n_in,
                              void* d_out, int out_size){
    (void)in_sizes; (void)n_in; (void)out_size;
    const float* x    = (const float*)d_in[0];
    const int*   ei   = (const int*)  d_in[1];
    const float* ea   = (const float*)d_in[2];
    const float* hnh  = (const float*)d_in[3];
    const float* hnc  = (const float*)d_in[4];
    const float* heh  = (const float*)d_in[5];
    const float* hec  = (const float*)d_in[6];
    const float* nWih = (const float*)d_in[7];
    const float* nWhh = (const float*)d_in[8];
    const float* nb   = (const float*)d_in[9];
    const float* eWih = (const float*)d_in[10];
    const float* eWhh = (const float*)d_in[11];
    const float* eb   = (const float*)d_in[12];
    const float* gatW = (const float*)d_in[13];
    const float* attS = (const float*)d_in[14];
    const float* attD = (const float*)d_in[15];
    const float* gatB = (const float*)d_in[16];
    const float* emW1 = (const float*)d_in[17];
    const float* emb1 = (const float*)d_in[18];
    const float* emW2 = (const float*)d_in[19];
    const float* emb2 = (const float*)d_in[20];
    const float* nmW1 = (const float*)d_in[21];
    const float* nmb1 = (const float*)d_in[22];
    const float* nmW2 = (const float*)d_in[23];
    const float* nmb2 = (const float*)d_in[24];
    float* out = (float*)d_out;

    static const int nlstm_smem = (256*64 + 256*5 + 256)*4;      // 71680
    static const int gproj_smem = (25600 + 16*96)*4;             // 108544
    cudaFuncSetAttribute(k_node_lstm, cudaFuncAttributeMaxDynamicSharedMemorySize, nlstm_smem);
    cudaFuncSetAttribute(k_gat_proj,  cudaFuncAttributeMaxDynamicSharedMemorySize, gproj_smem);

    k_init<<<592, 256>>>();
    k_edge_lstm<<<(Ee+255)/256, 256>>>(ea, ei, heh, hec, eWih, eWhh, eb, out);
    k_node_lstm<<<(Nn+255)/256, 256, nlstm_smem>>>(x, hnh, hnc, nWih, nWhh, nb, out);
    k_enc_div<<<(Nn*32+255)/256, 256>>>();
    k_gat_proj<<<296, 512, gproj_smem>>>(gatW);
    k_att<<<(Nn*4+255)/256, 256>>>(attS, attD);
    k_edge_max<<<(Ee*4+255)/256, 256>>>(ei);
    k_den_init<<<(Nn*4+255)/256, 256>>>();
    k_edge_exp<<<(Ee*4+255)/256, 256>>>(ei);
    k_self_msg<<<(Nn*64+255)/256, 256>>>();
    k_msg<<<(Ee+7)/8, 256>>>(ei);
    k_xgat_fin<<<(Nn*64+255)/256, 256>>>(gatB);
    k_pq<<<444, 512>>>(emW1, emb1);
    k_edge_mlp<<<592, 256>>>(ei, ea, emW1, emW2, emb2);
    k_node_mlp<<<444, 256>>>(nmW1, nmb1, nmW2, nmb2, out);
}

// round 3
// speedup vs baseline: 1.8002x; 1.0422x over previous
#include <cuda_runtime.h>
#include <math.h>

#define Nn 50000
#define Ee 400000
#define NBLK 196   // ceil(Nn/256)

// output packing: out[N*4], nh[N*64], nc[N*64], eh[E*32], ec[E*32]
#define OUT_OFF 0
#define NH_OFF  (Nn*4)
#define NC_OFF  (NH_OFF + Nn*64)
#define EH_OFF  (NC_OFF + Nn*64)
#define EC_OFF  (EH_OFF + Ee*32)

// ---------------- scratch (device globals; no allocation allowed) ----------
__device__ int   g_cnti[Nn];
__device__ int   g_bsum[256];
__device__ int   g_boff[256];
__device__ int   g_off[Nn+1];
__device__ int   g_cursor[Nn];
__device__ int   g_eid[Ee];      // CSR-by-dst: edge ids
__device__ int   g_esrc[Ee];     // CSR-by-dst: src node ids
__device__ float g_cntf[Nn];
__device__ float g_xcat[Nn*96];
__device__ float g_xh[Nn*256];   // [n, head, 64]
__device__ float g_as[Nn*4];
__device__ float g_ad[Nn*4];
__device__ float g_xgat[Nn*64];
__device__ float g_P[Nn*64];
__device__ float g_Q[Nn*64];
__device__ float g_elat[Ee*32];

__device__ __forceinline__ float fsig(float x){ return __fdividef(1.f, 1.f+__expf(-x)); }
__device__ __forceinline__ float ftanhf(float x){ return __fdividef(2.f, 1.f+__expf(-2.f*x)) - 1.f; }
__device__ __forceinline__ float leaky(float x){ return x > 0.f ? x : 0.2f*x; }

// ================= CSR build =================
__global__ void k_zero_cnt(){
    int t = blockIdx.x*blockDim.x + threadIdx.x;
    if (t < Nn) g_cnti[t] = 0;
}
__global__ void k_count(const int* __restrict__ ei){
    int e = blockIdx.x*blockDim.x + threadIdx.x;
    if (e < Ee) atomicAdd(&g_cnti[ei[Ee+e]], 1);
}
__global__ void k_scan1(){
    __shared__ int s[256];
    int i = blockIdx.x*256 + threadIdx.x;
    s[threadIdx.x] = (i < Nn) ? g_cnti[i] : 0;
    __syncthreads();
    for (int o=128; o; o>>=1){
        if (threadIdx.x < o) s[threadIdx.x] += s[threadIdx.x+o];
        __syncthreads();
    }
    if (threadIdx.x == 0) g_bsum[blockIdx.x] = s[0];
}
__global__ void k_scan2(){
    __shared__ int s[256];
    int t = threadIdx.x;
    s[t] = (t < NBLK) ? g_bsum[t] : 0;
    __syncthreads();
    if (t == 0){
        int run = 0;
        for (int i=0;i<NBLK;i++){ int v=s[i]; s[i]=run; run+=v; }
    }
    __syncthreads();
    if (t < NBLK) g_boff[t] = s[t];
}
__global__ void k_scan3(){
    __shared__ int s[256];
    int t = threadIdx.x;
    int i = blockIdx.x*256 + t;
    int cnt = (i < Nn) ? g_cnti[i] : 0;
    s[t] = cnt;
    __syncthreads();
    for (int o=1; o<256; o<<=1){
        int v = (t >= o) ? s[t-o] : 0;
        __syncthreads();
        s[t] += v;
        __syncthreads();
    }
    int off = g_boff[blockIdx.x] + s[t] - cnt;   // exclusive
    if (i < Nn){
        g_off[i] = off;
        g_cursor[i] = off;
        g_cntf[i] = (float)cnt;
        if (i == Nn-1) g_off[Nn] = off + cnt;
    }
}
__global__ void k_bin(const int* __restrict__ ei){
    int e = blockIdx.x*blockDim.x + threadIdx.x;
    if (e >= Ee) return;
    int d = ei[Ee+e];
    int p = atomicAdd(&g_cursor[d], 1);
    g_eid[p]  = e;
    g_esrc[p] = ei[e];
}

// ---------------- K1: edge LSTM (thread/edge, float4 broadcast LDS) --------
__global__ void __launch_bounds__(256) k_edge_lstm(
        const float* __restrict__ ea,
        const float* __restrict__ h0, const float* __restrict__ c0,
        const float* __restrict__ Wih, const float* __restrict__ Whh,
        const float* __restrict__ b, float* __restrict__ outp){
    __shared__ float4 sW4[128*8];    // Whh [row][k/4]
    __shared__ float sWih[256];
    __shared__ float sb[128];
    {
        float* sw = (float*)sW4;
        for (int i=threadIdx.x; i<4096; i+=256) sw[i] = Whh[i];
        for (int i=threadIdx.x; i<256;  i+=256) sWih[i] = Wih[i];
        for (int i=threadIdx.x; i<128;  i+=256) sb[i] = b[i];
    }
    __syncthreads();
    int e = blockIdx.x*256 + threadIdx.x;
    if (e >= Ee) return;

    float2 xv = ((const float2*)ea)[e];
    float4 h4[8];
    const float4* h0v = (const float4*)h0;
    #pragma unroll
    for (int i=0;i<8;i++) h4[i] = h0v[e*8+i];
    const float4* c0v = (const float4*)c0;
    float4* outv = (float4*)outp;

    #pragma unroll 1
    for (int j0=0;j0<32;j0+=4){
        float acc[4][4];       // [jj][gate]
        #pragma unroll
        for (int g=0; g<4; g++)
            #pragma unroll
            for (int jj=0; jj<4; jj++){
                int row = g*32 + j0 + jj;
                acc[jj][g] = sb[row] + xv.x*sWih[2*row] + xv.y*sWih[2*row+1];
            }
        #pragma unroll
        for (int k4=0; k4<8; k4++){
            float4 hk = h4[k4];
            #pragma unroll
            for (int g=0; g<4; g++)
                #pragma unroll
                for (int jj=0; jj<4; jj++){
                    float4 w = sW4[(g*32 + j0 + jj)*8 + k4];
                    acc[jj][g] += hk.x*w.x + hk.y*w.y + hk.z*w.z + hk.w*w.w;
                }
        }
        float4 cv = c0v[e*8 + (j0>>2)];
        float cc[4] = {cv.x, cv.y, cv.z, cv.w};
        float h2a[4], c2a[4];
        #pragma unroll
        for (int jj=0; jj<4; jj++){
            float c2 = fsig(acc[jj][1])*cc[jj] + fsig(acc[jj][0])*ftanhf(acc[jj][2]);
            float h2 = fsig(acc[jj][3])*ftanhf(c2);
            h2a[jj]=h2; c2a[jj]=c2;
        }
        outv[(EH_OFF + e*32 + j0)>>2] = make_float4(h2a[0],h2a[1],h2a[2],h2a[3]);
        outv[(EC_OFF + e*32 + j0)>>2] = make_float4(c2a[0],c2a[1],c2a[2],c2a[3]);
    }
}

// ---------------- K2: node LSTM (thread/node, Whh fully in dyn smem) -------
__global__ void __launch_bounds__(256) k_node_lstm(
        const float* __restrict__ x, const float* __restrict__ h0,
        const float* __restrict__ c0, const float* __restrict__ Wih,
        const float* __restrict__ Whh, const float* __restrict__ b,
        float* __restrict__ outp){
    extern __shared__ float dyn[];
    float4* sW4 = (float4*)dyn;             // 256*16 float4
    float*  sWih = dyn + 256*64;            // 256*5
    float*  sb   = sWih + 256*5;            // 256
    {
        float* sw = dyn;
        for (int i=threadIdx.x; i<256*64; i+=256) sw[i] = Whh[i];
        for (int i=threadIdx.x; i<256*5;  i+=256) sWih[i] = Wih[i];
        for (int i=threadIdx.x; i<256;    i+=256) sb[i] = b[i];
    }
    __syncthreads();
    int node = blockIdx.x*256 + threadIdx.x;
    if (node >= Nn) return;

    float xr[5];
    #pragma unroll
    for (int k=0;k<5;k++) xr[k] = x[node*5+k];
    float4 h4[16];
    const float4* h0v = (const float4*)h0;
    #pragma unroll
    for (int i=0;i<16;i++) h4[i] = h0v[node*16+i];
    const float4* c0v = (const float4*)c0;
    float4* outv = (float4*)outp;

    #pragma unroll 1
    for (int j0=0;j0<64;j0+=4){
        float acc[4][4];
        #pragma unroll
        for (int g=0; g<4; g++)
            #pragma unroll
            for (int jj=0; jj<4; jj++){
                int row = g*64 + j0 + jj;
                float a = sb[row];
                #pragma unroll
                for (int k=0;k<5;k++) a += xr[k]*sWih[row*5+k];
                acc[jj][g] = a;
            }
        #pragma unroll
        for (int k4=0; k4<16; k4++){
            float4 hk = h4[k4];
            #pragma unroll
            for (int g=0; g<4; g++)
                #pragma unroll
                for (int jj=0; jj<4; jj++){
                    float4 w = sW4[(g*64 + j0 + jj)*16 + k4];
                    acc[jj][g] += hk.x*w.x + hk.y*w.y + hk.z*w.z + hk.w*w.w;
                }
        }
        float4 cv = c0v[node*16 + (j0>>2)];
        float cc[4] = {cv.x, cv.y, cv.z, cv.w};
        float h2a[4], c2a[4];
        #pragma unroll
        for (int jj=0; jj<4; jj++){
            float c2 = fsig(acc[jj][1])*cc[jj] + fsig(acc[jj][0])*ftanhf(acc[jj][2]);
            float h2 = fsig(acc[jj][3])*ftanhf(c2);
            h2a[jj]=h2; c2a[jj]=c2;
        }
        float4 h2v = make_float4(h2a[0],h2a[1],h2a[2],h2a[3]);
        outv[(NH_OFF + node*64 + j0)>>2] = h2v;
        outv[(NC_OFF + node*64 + j0)>>2] = make_float4(c2a[0],c2a[1],c2a[2],c2a[3]);
        ((float4*)g_xcat)[(node*96 + j0)>>2] = h2v;
    }
}

// ---------------- K3: enc gather: mean of eh over in-edges -> xcat ---------
__global__ void __launch_bounds__(256) k_enc_gather(const float* __restrict__ outp){
    int warp = threadIdx.x>>5, lane = threadIdx.x&31;
    int n = blockIdx.x*8 + warp;
    if (n >= Nn) return;
    int beg = g_off[n], end = g_off[n+1];
    float acc = 0.f;
    for (int i=beg; i<end; i++){
        int e = g_eid[i];
        acc += outp[EH_OFF + e*32 + lane];
    }
    g_xcat[n*96 + 64 + lane] = __fdividef(acc, fmaxf(g_cntf[n], 1.f));
}

// ---------------- K4: GAT projection + attention logits (fused) ------------
__global__ void __launch_bounds__(512) k_gat_proj(const float* __restrict__ W,
                                                  const float* __restrict__ att_s,
                                                  const float* __restrict__ att_d){
    extern __shared__ float dyn[];
    float* sW  = dyn;               // [256 rows][96] pad 100
    float* sxc = dyn + 25600;       // [16 warps][96]
    float* ss  = sxc + 16*96;       // 256
    float* sd  = ss + 256;          // 256
    for (int i=threadIdx.x; i<24576; i+=512){
        int r = i/96, k = i - r*96;
        sW[r*100 + k] = W[i];
    }
    for (int i=threadIdx.x; i<256; i+=512){ ss[i]=att_s[i]; sd[i]=att_d[i]; }
    __syncthreads();
    int warp = threadIdx.x>>5, lane = threadIdx.x&31;
    for (int base = blockIdx.x*16; base < Nn; base += gridDim.x*16){
        int node = base + warp;
        if (node < Nn){
            float* xc = &sxc[warp*96];
            xc[lane]    = g_xcat[node*96 + lane];
            xc[lane+32] = g_xcat[node*96 + 32 + lane];
            xc[lane+64] = g_xcat[node*96 + 64 + lane];
        }
        __syncwarp();
        if (node < Nn){
            float acc[8];
            #pragma unroll
            for (int i=0;i<8;i++) acc[i]=0.f;
            #pragma unroll 4
            for (int kk0=0; kk0<96; kk0+=4){
                float4 xv = *(const float4*)&sxc[warp*96 + kk0];
                #pragma unroll
                for (int i=0;i<8;i++){
                    float4 w = *(const float4*)&sW[(lane + 32*i)*100 + kk0];
                    acc[i] += xv.x*w.x + xv.y*w.y + xv.z*w.z + xv.w*w.w;
                }
            }
            #pragma unroll
            for (int i=0;i<8;i++) g_xh[node*256 + lane + 32*i] = acc[i];
            // attention logits: head h covers acc[2h], acc[2h+1]
            float asp[4], adp[4];
            #pragma unroll
            for (int h=0;h<4;h++){
                asp[h] = acc[2*h]*ss[h*64+lane] + acc[2*h+1]*ss[h*64+32+lane];
                adp[h] = acc[2*h]*sd[h*64+lane] + acc[2*h+1]*sd[h*64+32+lane];
            }
            #pragma unroll
            for (int off=16; off; off>>=1)
                #pragma unroll
                for (int h=0;h<4;h++){
                    asp[h] += __shfl_xor_sync(0xffffffff, asp[h], off);
                    adp[h] += __shfl_xor_sync(0xffffffff, adp[h], off);
                }
            if (lane == 0){
                *(float4*)&g_as[node*4] = make_float4(asp[0],asp[1],asp[2],asp[3]);
                *(float4*)&g_ad[node*4] = make_float4(adp[0],adp[1],adp[2],adp[3]);
            }
        }
        __syncwarp();
    }
}

// ---------------- K5: fused GAT softmax + aggregation (warp/dst, no atomics)
__global__ void __launch_bounds__(256) k_gat_fused(const float* __restrict__ bias){
    __shared__ float sbias[64];
    if (threadIdx.x < 64) sbias[threadIdx.x] = bias[threadIdx.x];
    __syncthreads();
    int warp = threadIdx.x>>5, lane = threadIdx.x&31;
    int n = blockIdx.x*8 + warp;
    if (n >= Nn) return;
    float4 adv = *(const float4*)&g_ad[n*4];
    float4 asv = *(const float4*)&g_as[n*4];
    float m[4];
    m[0]=leaky(asv.x+adv.x); m[1]=leaky(asv.y+adv.y);
    m[2]=leaky(asv.z+adv.z); m[3]=leaky(asv.w+adv.w);
    float self[4] = {m[0],m[1],m[2],m[3]};
    int beg = g_off[n], end = g_off[n+1];
    for (int i=beg+lane; i<end; i+=32){
        int s = g_esrc[i];
        float4 av = *(const float4*)&g_as[s*4];
        m[0]=fmaxf(m[0], leaky(av.x+adv.x));
        m[1]=fmaxf(m[1], leaky(av.y+adv.y));
        m[2]=fmaxf(m[2], leaky(av.z+adv.z));
        m[3]=fmaxf(m[3], leaky(av.w+adv.w));
    }
    #pragma unroll
    for (int off=16; off; off>>=1)
        #pragma unroll
        for (int h=0;h<4;h++) m[h] = fmaxf(m[h], __shfl_xor_sync(0xffffffff, m[h], off));
    // self-loop seed
    float den[4], accA[4], accB[4];
    const float* xn = &g_xh[(size_t)n*256];
    #pragma unroll
    for (int h=0;h<4;h++){
        float w = __expf(self[h] - m[h]);
        den[h] = w;
        accA[h] = w * xn[h*64 + lane];
        accB[h] = w * xn[h*64 + 32 + lane];
    }
    // in-edges: all lanes cooperate on same edge (uniform weights, coalesced xh)
    for (int i=beg; i<end; i++){
        int s = g_esrc[i];
        float4 av = *(const float4*)&g_as[s*4];
        float w0 = __expf(leaky(av.x+adv.x) - m[0]);
        float w1 = __expf(leaky(av.y+adv.y) - m[1]);
        float w2 = __expf(leaky(av.z+adv.z) - m[2]);
        float w3 = __expf(leaky(av.w+adv.w) - m[3]);
        den[0]+=w0; den[1]+=w1; den[2]+=w2; den[3]+=w3;
        const float* xs = &g_xh[(size_t)s*256];
        accA[0] += w0*xs[lane];       accB[0] += w0*xs[32+lane];
        accA[1] += w1*xs[64+lane];    accB[1] += w1*xs[96+lane];
        accA[2] += w2*xs[128+lane];   accB[2] += w2*xs[160+lane];
        accA[3] += w3*xs[192+lane];   accB[3] += w3*xs[224+lane];
    }
    float rA = 0.f, rB = 0.f;
    #pragma unroll
    for (int h=0;h<4;h++){
        float inv = __fdividef(1.f, den[h]);
        rA += accA[h]*inv;
        rB += accB[h]*inv;
    }
    g_xgat[n*64 + lane]      = rA*0.25f + sbias[lane];
    g_xgat[n*64 + 32 + lane] = rB*0.25f + sbias[32 + lane];
}

// ---------------- K10a: P = W1a@xg + b1, Q = W1b@xg (persistent) -----------
__global__ void __launch_bounds__(512) k_pq(const float* __restrict__ W1, const float* __restrict__ b1){
    __shared__ float sW[128*68];
    __shared__ float sxg[16][64];
    __shared__ float sb1[64];
    for (int i=threadIdx.x; i<8192; i+=512){
        int r = i>>6, k = i&63;
        sW[r*68 + k] = (r < 64) ? W1[r*130 + k] : W1[(r-64)*130 + 64 + k];
    }
    for (int i=threadIdx.x; i<64; i+=512) sb1[i]=b1[i];
    __syncthreads();
    int warp = threadIdx.x>>5, lane = threadIdx.x&31;
    for (int base = blockIdx.x*16; base < Nn; base += gridDim.x*16){
        int n = base + warp;
        if (n < Nn){
            sxg[warp][lane]    = g_xgat[n*64+lane];
            sxg[warp][lane+32] = g_xgat[n*64+32+lane];
        }
        __syncwarp();
        if (n < Nn){
            float acc[4];
            acc[0]=sb1[lane]; acc[1]=sb1[lane+32]; acc[2]=0.f; acc[3]=0.f;
            #pragma unroll 4
            for (int k0=0;k0<64;k0+=4){
                float4 xv = *(const float4*)&sxg[warp][k0];
                #pragma unroll
                for (int i=0;i<4;i++){
                    float4 w = *(const float4*)&sW[(lane + 32*i)*68 + k0];
                    acc[i] += xv.x*w.x + xv.y*w.y + xv.z*w.z + xv.w*w.w;
                }
            }
            g_P[n*64+lane]=acc[0]; g_P[n*64+32+lane]=acc[1];
            g_Q[n*64+lane]=acc[2]; g_Q[n*64+32+lane]=acc[3];
        }
        __syncwarp();
    }
}

// ---------------- K10b: per-edge MLP -> e_lat (no atomics) -----------------
__global__ void __launch_bounds__(256) k_edge_mlp(
        const int* __restrict__ ei, const float* __restrict__ ea,
        const float* __restrict__ W1, const float* __restrict__ W2,
        const float* __restrict__ b2){
    __shared__ float sW2[32*68];   // [l][j] pad 68
    __shared__ float sw128[64], sw129[64], sb2[32];
    __shared__ float sh1[8][64];
    for (int i=threadIdx.x; i<2048; i+=256){
        int l = i>>6, j = i&63;
        sW2[l*68+j] = W2[l*64+j];
    }
    for (int i=threadIdx.x; i<64; i+=256){
        sw128[i]=W1[i*130+128]; sw129[i]=W1[i*130+129];
    }
    if (threadIdx.x < 32) sb2[threadIdx.x]=b2[threadIdx.x];
    __syncthreads();
    int warp = threadIdx.x>>5, lane = threadIdx.x&31;
    for (int e = blockIdx.x*8 + warp; e < Ee; e += gridDim.x*8){
        int s = ei[e], d = ei[Ee+e];
        float2 ev = ((const float2*)ea)[e];
        float h0 = fmaxf(g_P[s*64+lane]    + g_Q[d*64+lane]    + ev.x*sw128[lane]    + ev.y*sw129[lane],    0.f);
        float h1 = fmaxf(g_P[s*64+32+lane] + g_Q[d*64+32+lane] + ev.x*sw128[32+lane] + ev.y*sw129[32+lane], 0.f);
        sh1[warp][lane]=h0; sh1[warp][lane+32]=h1;
        __syncwarp();
        float acc = sb2[lane];
        #pragma unroll
        for (int j0=0;j0<64;j0+=4){
            float4 hv = *(const float4*)&sh1[warp][j0];
            float4 w  = *(const float4*)&sW2[lane*68 + j0];
            acc += hv.x*w.x + hv.y*w.y + hv.z*w.z + hv.w*w.w;
        }
        g_elat[e*32 + lane] = acc;
        __syncwarp();
    }
}

// ---------------- K11: node MLP (+ agg gather) -> out ----------------------
__global__ void __launch_bounds__(256) k_node_mlp(
        const float* __restrict__ W1, const float* __restrict__ b1,
        const float* __restrict__ W2, const float* __restrict__ b2,
        float* __restrict__ outp){
    __shared__ float sW1[64*100];
    __shared__ float sW2[4*64];
    __shared__ float sb1[64];
    __shared__ float snin[8][96];
    for (int i=threadIdx.x; i<6144; i+=256){
        int r = i/96, k = i - r*96;
        sW1[r*100 + k] = W1[i];
    }
    for (int i=threadIdx.x; i<256; i+=256) sW2[i]=W2[i];
    for (int i=threadIdx.x; i<64;  i+=256) sb1[i]=b1[i];
    __syncthreads();
    int warp = threadIdx.x>>5, lane = threadIdx.x&31;
    for (int base = blockIdx.x*8; base < Nn; base += gridDim.x*8){
        int n = base + warp;
        if (n < Nn){
            snin[warp][lane]    = g_xgat[n*64+lane];
            snin[warp][32+lane] = g_xgat[n*64+32+lane];
            int beg = g_off[n], end = g_off[n+1];
            float agg = 0.f;
            for (int i=beg; i<end; i++){
                int e = g_eid[i];
                agg += g_elat[e*32 + lane];
            }
            snin[warp][64+lane] = __fdividef(agg, fmaxf(g_cntf[n],1.f));
        }
        __syncwarp();
        if (n < Nn){
            float a0=sb1[lane], a1=sb1[lane+32];
            #pragma unroll 4
            for (int k0=0;k0<96;k0+=4){
                float4 xv = *(const float4*)&snin[warp][k0];
                float4 w0 = *(const float4*)&sW1[lane*100 + k0];
                float4 w1 = *(const float4*)&sW1[(lane+32)*100 + k0];
                a0 += xv.x*w0.x + xv.y*w0.y + xv.z*w0.z + xv.w*w0.w;
                a1 += xv.x*w1.x + xv.y*w1.y + xv.z*w1.z + xv.w*w1.w;
            }
            a0 = fmaxf(a0,0.f); a1 = fmaxf(a1,0.f);
            float p0 = a0*sW2[0*64+lane] + a1*sW2[0*64+32+lane];
            float p1 = a0*sW2[1*64+lane] + a1*sW2[1*64+32+lane];
            float p2 = a0*sW2[2*64+lane] + a1*sW2[2*64+32+lane];
            float p3 = a0*sW2[3*64+lane] + a1*sW2[3*64+32+lane];
            #pragma unroll
            for (int off=16; off; off>>=1){
                p0 += __shfl_down_sync(0xffffffff, p0, off);
                p1 += __shfl_down_sync(0xffffffff, p1, off);
                p2 += __shfl_down_sync(0xffffffff, p2, off);
                p3 += __shfl_down_sync(0xffffffff, p3, off);
            }
            if (lane == 0){
                outp[OUT_OFF + n*4+0] = p0 + b2[0];
                outp[OUT_OFF + n*4+1] = p1 + b2[1];
                outp[OUT_OFF + n*4+2] = p2 + b2[2];
                outp[OUT_OFF + n*4+3] = p3 + b2[3];
            }
        }
        __syncwarp();
    }
}

extern "C" void kernel_launch(void* const* d_in, const int* in_sizes, int n_in,
                              void* d_out, int out_size){
    (void)in_sizes; (void)n_in; (void)out_size;
    const float* x    = (const float*)d_in[0];
    const int*   ei   = (const int*)  d_in[1];
    const float* ea   = (const float*)d_in[2];
    const float* hnh  = (const float*)d_in[3];
    const float* hnc  = (const float*)d_in[4];
    const float* heh  = (const float*)d_in[5];
    const float* hec  = (const float*)d_in[6];
    const float* nWih = (const float*)d_in[7];
    const float* nWhh = (const float*)d_in[8];
    const float* nb   = (const float*)d_in[9];
    const float* eWih = (const float*)d_in[10];
    const float* eWhh = (const float*)d_in[11];
    const float* eb   = (const float*)d_in[12];
    const float* gatW = (const float*)d_in[13];
    const float* attS = (const float*)d_in[14];
    const float* attD = (const float*)d_in[15];
    const float* gatB = (const float*)d_in[16];
    const float* emW1 = (const float*)d_in[17];
    const float* emb1 = (const float*)d_in[18];
    const float* emW2 = (const float*)d_in[19];
    const float* emb2 = (const float*)d_in[20];
    const float* nmW1 = (const float*)d_in[21];
    const float* nmb1 = (const float*)d_in[22];
    const float* nmW2 = (const float*)d_in[23];
    const float* nmb2 = (const float*)d_in[24];
    float* out = (float*)d_out;

    static const int nlstm_smem = (256*64 + 256*5 + 256)*4;           // 71680
    static const int gproj_smem = (25600 + 16*96 + 512)*4;            // 110592
    cudaFuncSetAttribute(k_node_lstm, cudaFuncAttributeMaxDynamicSharedMemorySize, nlstm_smem);
    cudaFuncSetAttribute(k_gat_proj,  cudaFuncAttributeMaxDynamicSharedMemorySize, gproj_smem);

    // CSR build
    k_zero_cnt<<<NBLK, 256>>>();
    k_count<<<(Ee+255)/256, 256>>>(ei);
    k_scan1<<<NBLK, 256>>>();
    k_scan2<<<1, 256>>>();
    k_scan3<<<NBLK, 256>>>();
    k_bin<<<(Ee+255)/256, 256>>>(ei);

    // encoders
    k_edge_lstm<<<(Ee+255)/256, 256>>>(ea, heh, hec, eWih, eWhh, eb, out);
    k_node_lstm<<<(Nn+255)/256, 256, nlstm_smem>>>(x, hnh, hnc, nWih, nWhh, nb, out);
    k_enc_gather<<<(Nn+7)/8, 256>>>(out);

    // GAT
    k_gat_proj<<<296, 512, gproj_smem>>>(gatW, attS, attD);
    k_gat_fused<<<(Nn+7)/8, 256>>>(gatB);

    // GraphNetworkBlock
    k_pq<<<444, 512>>>(emW1, emb1);
    k_edge_mlp<<<592, 256>>>(ei, ea, emW1, emW2, emb2);
    k_node_mlp<<<444, 256>>>(nmW1, nmb1, nmW2, nmb2, out);
}

// round 4
// speedup vs baseline: 2.2242x; 1.2355x over previous
#include <cuda_runtime.h>
#include <math.h>

#define Nn 50000
#define Ee 400000
#define NBLK 196   // ceil(Nn/256)

// output packing: out[N*4], nh[N*64], nc[N*64], eh[E*32], ec[E*32]
#define OUT_OFF 0
#define NH_OFF  (Nn*4)
#define NC_OFF  (NH_OFF + Nn*64)
#define EH_OFF  (NC_OFF + Nn*64)
#define EC_OFF  (EH_OFF + Ee*32)

// ---------------- scratch ----------------
__device__ int   g_cnti[Nn];
__device__ int   g_bsum[256];
__device__ int   g_boff[256];
__device__ int   g_off[Nn+1];
__device__ int   g_cursor[Nn];
__device__ int   g_eid[Ee];
__device__ int   g_esrc[Ee];
__device__ float g_cntf[Nn];
__device__ float g_xcat[Nn*96];
__device__ float g_xh[Nn*256];
__device__ float g_as[Nn*4];
__device__ float g_ad[Nn*4];
__device__ float g_xgat[Nn*64];
__device__ float g_P[Nn*64];
__device__ float g_Q[Nn*64];
__device__ float g_elat[Ee*32];
__device__ float g_agg[Nn*32];

typedef unsigned long long u64;
__device__ __forceinline__ u64 pk2(float lo, float hi){ u64 r; asm("mov.b64 %0, {%1,%2};" : "=l"(r) : "f"(lo), "f"(hi)); return r; }
__device__ __forceinline__ u64 dup2(float v){ return pk2(v,v); }
__device__ __forceinline__ void fma2(u64 &acc, u64 a, u64 b){ asm("fma.rn.f32x2 %0, %1, %2, %0;" : "+l"(acc) : "l"(a), "l"(b)); }
__device__ __forceinline__ void up2(u64 v, float &lo, float &hi){ asm("mov.b64 {%0,%1}, %2;" : "=f"(lo), "=f"(hi) : "l"(v)); }

__device__ __forceinline__ float fsig(float x){ return __fdividef(1.f, 1.f+__expf(-x)); }
__device__ __forceinline__ float ftanhf(float x){ return __fdividef(2.f, 1.f+__expf(-2.f*x)) - 1.f; }
__device__ __forceinline__ float leaky(float x){ return x > 0.f ? x : 0.2f*x; }

// ================= CSR build =================
__global__ void k_zero_cnt(){
    int t = blockIdx.x*blockDim.x + threadIdx.x;
    if (t < Nn) g_cnti[t] = 0;
}
__global__ void k_count(const int* __restrict__ ei){
    int e = blockIdx.x*blockDim.x + threadIdx.x;
    if (e < Ee) atomicAdd(&g_cnti[ei[Ee+e]], 1);
}
__global__ void k_scan1(){
    __shared__ int s[256];
    int i = blockIdx.x*256 + threadIdx.x;
    s[threadIdx.x] = (i < Nn) ? g_cnti[i] : 0;
    __syncthreads();
    for (int o=128; o; o>>=1){
        if (threadIdx.x < o) s[threadIdx.x] += s[threadIdx.x+o];
        __syncthreads();
    }
    if (threadIdx.x == 0) g_bsum[blockIdx.x] = s[0];
}
__global__ void k_scan2(){
    __shared__ int s[256];
    int t = threadIdx.x;
    s[t] = (t < NBLK) ? g_bsum[t] : 0;
    __syncthreads();
    if (t == 0){
        int run = 0;
        for (int i=0;i<NBLK;i++){ int v=s[i]; s[i]=run; run+=v; }
    }
    __syncthreads();
    if (t < NBLK) g_boff[t] = s[t];
}
__global__ void k_scan3(){
    __shared__ int s[256];
    int t = threadIdx.x;
    int i = blockIdx.x*256 + t;
    int cnt = (i < Nn) ? g_cnti[i] : 0;
    s[t] = cnt;
    __syncthreads();
    for (int o=1; o<256; o<<=1){
        int v = (t >= o) ? s[t-o] : 0;
        __syncthreads();
        s[t] += v;
        __syncthreads();
    }
    int off = g_boff[blockIdx.x] + s[t] - cnt;
    if (i < Nn){
        g_off[i] = off;
        g_cursor[i] = off;
        g_cntf[i] = (float)cnt;
        if (i == Nn-1) g_off[Nn] = off + cnt;
    }
}
__global__ void k_bin(const int* __restrict__ ei){
    int e = blockIdx.x*blockDim.x + threadIdx.x;
    if (e >= Ee) return;
    int d = ei[Ee+e];
    int p = atomicAdd(&g_cursor[d], 1);
    g_eid[p]  = e;
    g_esrc[p] = ei[e];
}

// ---------- K1: edge LSTM, f32x2 row-pair quad-packed ----------
__global__ void __launch_bounds__(256) k_edge_lstm(
        const float* __restrict__ ea,
        const float* __restrict__ h0, const float* __restrict__ c0,
        const float* __restrict__ Wih, const float* __restrict__ Whh,
        const float* __restrict__ b, float* __restrict__ outp){
    __shared__ float4 sQ[16*64];    // quad[(k2)*64 + jp]
    __shared__ float sWih[256];
    __shared__ float sb[128];
    {
        float* sQf = (float*)sQ;
        for (int i=threadIdx.x; i<4096; i+=256){
            int r = i>>5, k = i&31;
            sQf[((k>>1)*64 + (r>>1))*4 + (r&1) + 2*(k&1)] = Whh[i];
        }
        for (int i=threadIdx.x; i<256; i+=256) sWih[i] = Wih[i];
        for (int i=threadIdx.x; i<128; i+=256) sb[i] = b[i];
    }
    __syncthreads();
    int e = blockIdx.x*256 + threadIdx.x;
    if (e >= Ee) return;

    float2 xv = ((const float2*)ea)[e];
    float h[32];
    {
        const float4* h0v = (const float4*)h0;
        #pragma unroll
        for (int i=0;i<8;i++){
            float4 v = h0v[e*8+i];
            h[4*i]=v.x; h[4*i+1]=v.y; h[4*i+2]=v.z; h[4*i+3]=v.w;
        }
    }
    const float4* c0v = (const float4*)c0;
    float4* outv = (float4*)outp;
    const ulonglong2* sQ2 = (const ulonglong2*)sQ;

    #pragma unroll 1
    for (int j0=0;j0<32;j0+=4){
        u64 acc[4][2];   // [gate][pair]
        #pragma unroll
        for (int g=0; g<4; g++)
            #pragma unroll
            for (int p=0; p<2; p++){
                int r0 = g*32 + j0 + 2*p;
                float alo = sb[r0]   + xv.x*sWih[2*r0]   + xv.y*sWih[2*r0+1];
                float ahi = sb[r0+1] + xv.x*sWih[2*r0+2] + xv.y*sWih[2*r0+3];
                acc[g][p] = pk2(alo, ahi);
            }
        #pragma unroll
        for (int k2=0; k2<16; k2++){
            u64 xlo = dup2(h[2*k2]);
            u64 xhi = dup2(h[2*k2+1]);
            #pragma unroll
            for (int g=0; g<4; g++)
                #pragma unroll
                for (int p=0; p<2; p++){
                    ulonglong2 q = sQ2[k2*64 + g*16 + (j0>>1) + p];
                    fma2(acc[g][p], xlo, q.x);
                    fma2(acc[g][p], xhi, q.y);
                }
        }
        float gi[4], gf[4], gg[4], go[4];
        #pragma unroll
        for (int p=0; p<2; p++){
            up2(acc[0][p], gi[2*p], gi[2*p+1]);
            up2(acc[1][p], gf[2*p], gf[2*p+1]);
            up2(acc[2][p], gg[2*p], gg[2*p+1]);
            up2(acc[3][p], go[2*p], go[2*p+1]);
        }
        float4 cv = c0v[e*8 + (j0>>2)];
        float cc[4] = {cv.x, cv.y, cv.z, cv.w};
        float h2a[4], c2a[4];
        #pragma unroll
        for (int u=0; u<4; u++){
            float c2 = fsig(gf[u])*cc[u] + fsig(gi[u])*ftanhf(gg[u]);
            float h2 = fsig(go[u])*ftanhf(c2);
            h2a[u]=h2; c2a[u]=c2;
        }
        outv[(EH_OFF + e*32 + j0)>>2] = make_float4(h2a[0],h2a[1],h2a[2],h2a[3]);
        outv[(EC_OFF + e*32 + j0)>>2] = make_float4(c2a[0],c2a[1],c2a[2],c2a[3]);
    }
}

// ---------- K2: node LSTM, f32x2 quad-packed ----------
__global__ void __launch_bounds__(128) k_node_lstm(
        const float* __restrict__ x, const float* __restrict__ h0,
        const float* __restrict__ c0, const float* __restrict__ Wih,
        const float* __restrict__ Whh, const float* __restrict__ b,
        float* __restrict__ outp){
    extern __shared__ float dyn[];
    float* sQf  = dyn;                  // 16384 floats
    float* sWih = dyn + 16384;          // 1280
    float* sb   = sWih + 1280;          // 256
    for (int i=threadIdx.x; i<16384; i+=128){
        int r = i>>6, k = i&63;
        sQf[((k>>1)*128 + (r>>1))*4 + (r&1) + 2*(k&1)] = Whh[i];
    }
    for (int i=threadIdx.x; i<1280; i+=128) sWih[i] = Wih[i];
    for (int i=threadIdx.x; i<256;  i+=128) sb[i] = b[i];
    __syncthreads();
    int node = blockIdx.x*128 + threadIdx.x;
    if (node >= Nn) return;

    float xr[5];
    #pragma unroll
    for (int k=0;k<5;k++) xr[k] = x[node*5+k];
    float h[64];
    {
        const float4* h0v = (const float4*)h0;
        #pragma unroll
        for (int i=0;i<16;i++){
            float4 v = h0v[node*16+i];
            h[4*i]=v.x; h[4*i+1]=v.y; h[4*i+2]=v.z; h[4*i+3]=v.w;
        }
    }
    const float4* c0v = (const float4*)c0;
    float4* outv = (float4*)outp;
    const ulonglong2* sQ2 = (const ulonglong2*)sQf;

    #pragma unroll 1
    for (int j0=0;j0<64;j0+=4){
        u64 acc[4][2];
        #pragma unroll
        for (int g=0; g<4; g++)
            #pragma unroll
            for (int p=0; p<2; p++){
                int r0 = g*64 + j0 + 2*p;
                float alo = sb[r0], ahi = sb[r0+1];
                #pragma unroll
                for (int k=0;k<5;k++){
                    alo += xr[k]*sWih[r0*5+k];
                    ahi += xr[k]*sWih[(r0+1)*5+k];
                }
                acc[g][p] = pk2(alo, ahi);
            }
        #pragma unroll
        for (int k2=0; k2<32; k2++){
            u64 xlo = dup2(h[2*k2]);
            u64 xhi = dup2(h[2*k2+1]);
            #pragma unroll
            for (int g=0; g<4; g++)
                #pragma unroll
                for (int p=0; p<2; p++){
                    ulonglong2 q = sQ2[k2*128 + g*32 + (j0>>1) + p];
                    fma2(acc[g][p], xlo, q.x);
                    fma2(acc[g][p], xhi, q.y);
                }
        }
        float gi[4], gf[4], gg[4], go[4];
        #pragma unroll
        for (int p=0; p<2; p++){
            up2(acc[0][p], gi[2*p], gi[2*p+1]);
            up2(acc[1][p], gf[2*p], gf[2*p+1]);
            up2(acc[2][p], gg[2*p], gg[2*p+1]);
            up2(acc[3][p], go[2*p], go[2*p+1]);
        }
        float4 cv = c0v[node*16 + (j0>>2)];
        float cc[4] = {cv.x, cv.y, cv.z, cv.w};
        float h2a[4], c2a[4];
        #pragma unroll
        for (int u=0; u<4; u++){
            float c2 = fsig(gf[u])*cc[u] + fsig(gi[u])*ftanhf(gg[u]);
            float h2 = fsig(go[u])*ftanhf(c2);
            h2a[u]=h2; c2a[u]=c2;
        }
        float4 h2v = make_float4(h2a[0],h2a[1],h2a[2],h2a[3]);
        outv[(NH_OFF + node*64 + j0)>>2] = h2v;
        outv[(NC_OFF + node*64 + j0)>>2] = make_float4(c2a[0],c2a[1],c2a[2],c2a[3]);
        ((float4*)g_xcat)[(node*96 + j0)>>2] = h2v;
    }
}

// ---------- K3: enc gather ----------
__global__ void __launch_bounds__(256) k_enc_gather(const float* __restrict__ outp){
    int warp = threadIdx.x>>5, lane = threadIdx.x&31;
    int n = blockIdx.x*8 + warp;
    if (n >= Nn) return;
    int beg = g_off[n], end = g_off[n+1];
    float acc = 0.f;
    for (int i=beg; i<end; i++){
        int e = g_eid[i];
        acc += outp[EH_OFF + e*32 + lane];
    }
    g_xcat[n*96 + 64 + lane] = __fdividef(acc, fmaxf(g_cntf[n], 1.f));
}

// ---------- K4: GAT projection + logits, thread/node quad-packed ----------
__global__ void __launch_bounds__(128) k_gat_proj(const float* __restrict__ W,
                                                  const float* __restrict__ att_s,
                                                  const float* __restrict__ att_d){
    extern __shared__ float dyn[];
    float* sQf = dyn;            // 24576 floats: quad[(k2)*128 + jp]
    float* ss  = dyn + 24576;    // 256
    float* sd  = ss + 256;       // 256
    for (int i=threadIdx.x; i<24576; i+=128){
        int r = i/96, k = i - r*96;
        sQf[((k>>1)*128 + (r>>1))*4 + (r&1) + 2*(k&1)] = W[i];
    }
    for (int i=threadIdx.x; i<256; i+=128){ ss[i]=att_s[i]; sd[i]=att_d[i]; }
    __syncthreads();
    int n = blockIdx.x*128 + threadIdx.x;
    if (n >= Nn) return;

    float xc[96];
    {
        const float4* xv = (const float4*)(g_xcat + n*96);
        #pragma unroll
        for (int i=0;i<24;i++){
            float4 v = xv[i];
            xc[4*i]=v.x; xc[4*i+1]=v.y; xc[4*i+2]=v.z; xc[4*i+3]=v.w;
        }
    }
    const ulonglong2* sQ2 = (const ulonglong2*)sQf;
    float asa[4] = {0,0,0,0}, ada[4] = {0,0,0,0};

    #pragma unroll 1
    for (int rb=0; rb<16; rb++){
        u64 acc[8];
        #pragma unroll
        for (int p=0;p<8;p++) acc[p] = 0ull;
        #pragma unroll
        for (int k2=0; k2<48; k2++){
            u64 xlo = dup2(xc[2*k2]);
            u64 xhi = dup2(xc[2*k2+1]);
            #pragma unroll
            for (int p=0;p<8;p++){
                ulonglong2 q = sQ2[k2*128 + rb*8 + p];
                fma2(acc[p], xlo, q.x);
                fma2(acc[p], xhi, q.y);
            }
        }
        float v[16];
        #pragma unroll
        for (int p=0;p<8;p++) up2(acc[p], v[2*p], v[2*p+1]);
        int hd = rb>>2;
        #pragma unroll
        for (int u=0;u<16;u++){
            int r = rb*16 + u;
            asa[hd] += v[u]*ss[r];
            ada[hd] += v[u]*sd[r];
        }
        float4* xh4 = (float4*)(g_xh + (size_t)n*256 + rb*16);
        xh4[0] = make_float4(v[0],v[1],v[2],v[3]);
        xh4[1] = make_float4(v[4],v[5],v[6],v[7]);
        xh4[2] = make_float4(v[8],v[9],v[10],v[11]);
        xh4[3] = make_float4(v[12],v[13],v[14],v[15]);
    }
    *(float4*)&g_as[n*4] = make_float4(asa[0],asa[1],asa[2],asa[3]);
    *(float4*)&g_ad[n*4] = make_float4(ada[0],ada[1],ada[2],ada[3]);
}

// ---------- K5: fused GAT softmax+aggregate (warp/dst) ----------
__global__ void __launch_bounds__(256) k_gat_fused(const float* __restrict__ bias){
    __shared__ float sbias[64];
    if (threadIdx.x < 64) sbias[threadIdx.x] = bias[threadIdx.x];
    __syncthreads();
    int warp = threadIdx.x>>5, lane = threadIdx.x&31;
    int n = blockIdx.x*8 + warp;
    if (n >= Nn) return;
    float4 adv = *(const float4*)&g_ad[n*4];
    float4 asv = *(const float4*)&g_as[n*4];
    float m[4];
    m[0]=leaky(asv.x+adv.x); m[1]=leaky(asv.y+adv.y);
    m[2]=leaky(asv.z+adv.z); m[3]=leaky(asv.w+adv.w);
    float self[4] = {m[0],m[1],m[2],m[3]};
    int beg = g_off[n], end = g_off[n+1];
    for (int i=beg+lane; i<end; i+=32){
        int s = g_esrc[i];
        float4 av = *(const float4*)&g_as[s*4];
        m[0]=fmaxf(m[0], leaky(av.x+adv.x));
        m[1]=fmaxf(m[1], leaky(av.y+adv.y));
        m[2]=fmaxf(m[2], leaky(av.z+adv.z));
        m[3]=fmaxf(m[3], leaky(av.w+adv.w));
    }
    #pragma unroll
    for (int off=16; off; off>>=1)
        #pragma unroll
        for (int h=0;h<4;h++) m[h] = fmaxf(m[h], __shfl_xor_sync(0xffffffff, m[h], off));
    float den[4], accA[4], accB[4];
    const float* xn = &g_xh[(size_t)n*256];
    #pragma unroll
    for (int h=0;h<4;h++){
        float w = __expf(self[h] - m[h]);
        den[h] = w;
        accA[h] = w * xn[h*64 + lane];
        accB[h] = w * xn[h*64 + 32 + lane];
    }
    for (int i=beg; i<end; i++){
        int s = g_esrc[i];
        float4 av = *(const float4*)&g_as[s*4];
        float w0 = __expf(leaky(av.x+adv.x) - m[0]);
        float w1 = __expf(leaky(av.y+adv.y) - m[1]);
        float w2 = __expf(leaky(av.z+adv.z) - m[2]);
        float w3 = __expf(leaky(av.w+adv.w) - m[3]);
        den[0]+=w0; den[1]+=w1; den[2]+=w2; den[3]+=w3;
        const float* xs = &g_xh[(size_t)s*256];
        accA[0] += w0*xs[lane];       accB[0] += w0*xs[32+lane];
        accA[1] += w1*xs[64+lane];    accB[1] += w1*xs[96+lane];
        accA[2] += w2*xs[128+lane];   accB[2] += w2*xs[160+lane];
        accA[3] += w3*xs[192+lane];   accB[3] += w3*xs[224+lane];
    }
    float rA = 0.f, rB = 0.f;
    #pragma unroll
    for (int h=0;h<4;h++){
        float inv = __fdividef(1.f, den[h]);
        rA += accA[h]*inv;
        rB += accB[h]*inv;
    }
    g_xgat[n*64 + lane]      = rA*0.25f + sbias[lane];
    g_xgat[n*64 + 32 + lane] = rB*0.25f + sbias[32 + lane];
}

// ---------- K6: P/Q, thread/node quad-packed ----------
__global__ void __launch_bounds__(256) k_pq(const float* __restrict__ W1, const float* __restrict__ b1){
    __shared__ float sQf[8192];      // quad[(k2)*64 + jp], 128 rows x 64 k
    __shared__ float sb1[64];
    for (int i=threadIdx.x; i<8192; i+=256){
        int R = i>>6, k = i&63;
        float v = (R < 64) ? W1[R*130 + k] : W1[(R-64)*130 + 64 + k];
        sQf[((k>>1)*64 + (R>>1))*4 + (R&1) + 2*(k&1)] = v;
    }
    for (int i=threadIdx.x; i<64; i+=256) sb1[i]=b1[i];
    __syncthreads();
    int n = blockIdx.x*256 + threadIdx.x;
    if (n >= Nn) return;

    float xg[64];
    {
        const float4* xv = (const float4*)(g_xgat + n*64);
        #pragma unroll
        for (int i=0;i<16;i++){
            float4 v = xv[i];
            xg[4*i]=v.x; xg[4*i+1]=v.y; xg[4*i+2]=v.z; xg[4*i+3]=v.w;
        }
    }
    const ulonglong2* sQ2 = (const ulonglong2*)sQf;
    #pragma unroll 1
    for (int rb=0; rb<8; rb++){
        u64 acc[8];
        #pragma unroll
        for (int p=0;p<8;p++){
            int r = rb*16 + 2*p;
            acc[p] = (rb < 4) ? pk2(sb1[r], sb1[r+1]) : 0ull;
        }
        #pragma unroll
        for (int k2=0; k2<32; k2++){
            u64 xlo = dup2(xg[2*k2]);
            u64 xhi = dup2(xg[2*k2+1]);
            #pragma unroll
            for (int p=0;p<8;p++){
                ulonglong2 q = sQ2[k2*64 + rb*8 + p];
                fma2(acc[p], xlo, q.x);
                fma2(acc[p], xhi, q.y);
            }
        }
        float v[16];
        #pragma unroll
        for (int p=0;p<8;p++) up2(acc[p], v[2*p], v[2*p+1]);
        float* dst = (rb < 4) ? (g_P + n*64 + rb*16) : (g_Q + n*64 + (rb-4)*16);
        float4* d4 = (float4*)dst;
        d4[0] = make_float4(v[0],v[1],v[2],v[3]);
        d4[1] = make_float4(v[4],v[5],v[6],v[7]);
        d4[2] = make_float4(v[8],v[9],v[10],v[11]);
        d4[3] = make_float4(v[12],v[13],v[14],v[15]);
    }
}

// ---------- K7: edge MLP, warp per 16 edges, f32x2 tiled layer-2 ----------
__global__ void __launch_bounds__(256) k_edge_mlp(
        const int* __restrict__ ei, const float* __restrict__ ea,
        const float* __restrict__ W1, const float* __restrict__ W2,
        const float* __restrict__ b2){
    __shared__ float sW2dq[32*33*4];   // dup-quad: [l][j2] = (w2j,w2j,w2j1,w2j1), pad 33
    __shared__ float sw128[64], sw129[64], sb2[32];
    extern __shared__ float sHf[];     // [8 warps][8 epair][32 j2] quads = 8192 floats
    for (int i=threadIdx.x; i<2048; i+=256){
        int l = i>>6, j = i&63;
        float v = W2[l*64+j];
        int base = (l*33 + (j>>1))*4 + 2*(j&1);
        sW2dq[base] = v; sW2dq[base+1] = v;
    }
    for (int i=threadIdx.x; i<64; i+=256){
        sw128[i]=W1[i*130+128]; sw129[i]=W1[i*130+129];
    }
    if (threadIdx.x < 32) sb2[threadIdx.x]=b2[threadIdx.x];
    __syncthreads();
    int warp = threadIdx.x>>5, lane = threadIdx.x&31;
    int base_e = (blockIdx.x*8 + warp)*16;
    if (base_e >= Ee) return;

    // phase 1: layer-1 for 16 edges, store dup-packed pairs
    float* myH = sHf + warp*1024;
    for (int el=0; el<16; el++){
        int e = base_e + el;
        int s = ei[e], d = ei[Ee+e];
        float2 ev = ((const float2*)ea)[e];
        float h0 = fmaxf(g_P[s*64+lane]    + g_Q[d*64+lane]    + ev.x*sw128[lane]    + ev.y*sw129[lane],    0.f);
        float h1 = fmaxf(g_P[s*64+32+lane] + g_Q[d*64+32+lane] + ev.x*sw128[32+lane] + ev.y*sw129[32+lane], 0.f);
        int ep = el>>1, c = el&1;
        int j = lane;
        myH[(ep*32 + (j>>1))*4 + 2*(j&1) + c] = h0;
        j = lane + 32;
        myH[(ep*32 + (j>>1))*4 + 2*(j&1) + c] = h1;
    }
    __syncwarp();
    // phase 2: layer-2 GEMM [32 out x 16 edges]
    u64 acc[8];
    #pragma unroll
    for (int ep=0;ep<8;ep++) acc[ep] = dup2(sb2[lane]);
    const ulonglong2* sW2q = (const ulonglong2*)sW2dq;
    const ulonglong2* sH2 = (const ulonglong2*)myH;
    #pragma unroll 4
    for (int j2=0; j2<32; j2++){
        ulonglong2 qw = sW2q[lane*33 + j2];
        #pragma unroll
        for (int ep=0;ep<8;ep++){
            ulonglong2 xq = sH2[ep*32 + j2];
            fma2(acc[ep], xq.x, qw.x);
            fma2(acc[ep], xq.y, qw.y);
        }
    }
    #pragma unroll
    for (int ep=0;ep<8;ep++){
        float o0, o1;
        up2(acc[ep], o0, o1);
        g_elat[(base_e + 2*ep)*32 + lane]   = o0;
        g_elat[(base_e + 2*ep+1)*32 + lane] = o1;
    }
}

// ---------- K8: agg gather (mean of e_lat over in-edges) ----------
__global__ void __launch_bounds__(256) k_agg_gather(){
    int warp = threadIdx.x>>5, lane = threadIdx.x&31;
    int n = blockIdx.x*8 + warp;
    if (n >= Nn) return;
    int beg = g_off[n], end = g_off[n+1];
    float acc = 0.f;
    for (int i=beg; i<end; i++){
        int e = g_eid[i];
        acc += g_elat[e*32 + lane];
    }
    g_agg[n*32 + lane] = __fdividef(acc, fmaxf(g_cntf[n], 1.f));
}

// ---------- K9: node MLP, thread/node quad-packed, fused layer-2 ----------
__global__ void __launch_bounds__(128) k_node_mlp(
        const float* __restrict__ W1, const float* __restrict__ b1,
        const float* __restrict__ W2, const float* __restrict__ b2,
        float* __restrict__ outp){
    __shared__ float sQf[6144];     // 64 rows x 96 k quads: [(k2)*32 + jp]
    __shared__ float sW2[256];      // [o*64 + r]
    __shared__ float sb1[64];
    for (int i=threadIdx.x; i<6144; i+=128){
        int r = i/96, k = i - r*96;
        sQf[((k>>1)*32 + (r>>1))*4 + (r&1) + 2*(k&1)] = W1[i];
    }
    for (int i=threadIdx.x; i<256; i+=128) sW2[i]=W2[i];
    for (int i=threadIdx.x; i<64;  i+=128) sb1[i]=b1[i];
    __syncthreads();
    int n = blockIdx.x*128 + threadIdx.x;
    if (n >= Nn) return;

    float xc[96];
    {
        const float4* xv = (const float4*)(g_xgat + n*64);
        #pragma unroll
        for (int i=0;i<16;i++){
            float4 v = xv[i];
            xc[4*i]=v.x; xc[4*i+1]=v.y; xc[4*i+2]=v.z; xc[4*i+3]=v.w;
        }
        const float4* av = (const float4*)(g_agg + n*32);
        #pragma unroll
        for (int i=0;i<8;i++){
            float4 v = av[i];
            xc[64+4*i]=v.x; xc[64+4*i+1]=v.y; xc[64+4*i+2]=v.z; xc[64+4*i+3]=v.w;
        }
    }
    const ulonglong2* sQ2 = (const ulonglong2*)sQf;
    float p[4] = {0,0,0,0};
    #pragma unroll 1
    for (int rb=0; rb<4; rb++){
        u64 acc[8];
        #pragma unroll
        for (int q=0;q<8;q++){
            int r = rb*16 + 2*q;
            acc[q] = pk2(sb1[r], sb1[r+1]);
        }
        #pragma unroll
        for (int k2=0; k2<48; k2++){
            u64 xlo = dup2(xc[2*k2]);
            u64 xhi = dup2(xc[2*k2+1]);
            #pragma unroll
            for (int q=0;q<8;q++){
                ulonglong2 w = sQ2[k2*32 + rb*8 + q];
                fma2(acc[q], xlo, w.x);
                fma2(acc[q], xhi, w.y);
            }
        }
        #pragma unroll
        for (int q=0;q<8;q++){
            float vlo, vhi;
            up2(acc[q], vlo, vhi);
            int r = rb*16 + 2*q;
            vlo = fmaxf(vlo, 0.f); vhi = fmaxf(vhi, 0.f);
            #pragma unroll
            for (int o=0;o<4;o++)
                p[o] += vlo*sW2[o*64 + r] + vhi*sW2[o*64 + r + 1];
        }
    }
    *(float4*)&outp[OUT_OFF + n*4] = make_float4(p[0]+b2[0], p[1]+b2[1], p[2]+b2[2], p[3]+b2[3]);
}

extern "C" void kernel_launch(void* const* d_in, const int* in_sizes, int n_in,
                              void* d_out, int out_size){
    (void)in_sizes; (void)n_in; (void)out_size;
    const float* x    = (const float*)d_in[0];
    const int*   ei   = (const int*)  d_in[1];
    const float* ea   = (const float*)d_in[2];
    const float* hnh  = (const float*)d_in[3];
    const float* hnc  = (const float*)d_in[4];
    const float* heh  = (const float*)d_in[5];
    const float* hec  = (const float*)d_in[6];
    const float* nWih = (const float*)d_in[7];
    const float* nWhh = (const float*)d_in[8];
    const float* nb   = (const float*)d_in[9];
    const float* eWih = (const float*)d_in[10];
    const float* eWhh = (const float*)d_in[11];
    const float* eb   = (const float*)d_in[12];
    const float* gatW = (const float*)d_in[13];
    const float* attS = (const float*)d_in[14];
    const float* attD = (const float*)d_in[15];
    const float* gatB = (const float*)d_in[16];
    const float* emW1 = (const float*)d_in[17];
    const float* emb1 = (const float*)d_in[18];
    const float* emW2 = (const float*)d_in[19];
    const float* emb2 = (const float*)d_in[20];
    const float* nmW1 = (const float*)d_in[21];
    const float* nmb1 = (const float*)d_in[22];
    const float* nmW2 = (const float*)d_in[23];
    const float* nmb2 = (const float*)d_in[24];
    float* out = (float*)d_out;

    static const int nlstm_smem = (16384 + 1280 + 256)*4;      // 71680
    static const int gproj_smem = (24576 + 512)*4;             // 100352
    static const int emlp_smem  = 8192*4;                      // 32768
    cudaFuncSetAttribute(k_node_lstm, cudaFuncAttributeMaxDynamicSharedMemorySize, nlstm_smem);
    cudaFuncSetAttribute(k_gat_proj,  cudaFuncAttributeMaxDynamicSharedMemorySize, gproj_smem);
    cudaFuncSetAttribute(k_edge_mlp,  cudaFuncAttributeMaxDynamicSharedMemorySize, emlp_smem);

    // CSR + encoders (edge_lstm placed at launch index 3 for ncu capture)
    k_zero_cnt<<<NBLK, 256>>>();
    k_count<<<(Ee+255)/256, 256>>>(ei);
    k_scan1<<<NBLK, 256>>>();
    k_edge_lstm<<<(Ee+255)/256, 256>>>(ea, heh, hec, eWih, eWhh, eb, out);
    k_scan2<<<1, 256>>>();
    k_scan3<<<NBLK, 256>>>();
    k_bin<<<(Ee+255)/256, 256>>>(ei);
    k_node_lstm<<<(Nn+127)/128, 128, nlstm_smem>>>(x, hnh, hnc, nWih, nWhh, nb, out);
    k_enc_gather<<<(Nn+7)/8, 256>>>(out);

    // GAT
    k_gat_proj<<<(Nn+127)/128, 128, gproj_smem>>>(gatW, attS, attD);
    k_gat_fused<<<(Nn+7)/8, 256>>>(gatB);

    // GraphNetworkBlock
    k_pq<<<(Nn+255)/256, 256>>>(emW1, emb1);
    k_edge_mlp<<<(Ee+127)/128, 256, emlp_smem>>>(ei, ea, emW1, emW2, emb2);
    k_agg_gather<<<(Nn+7)/8, 256>>>();
    k_node_mlp<<<(Nn+127)/128, 128>>>(nmW1, nmb1, nmW2, nmb2, out);
}

// round 5
// speedup vs baseline: 2.2561x; 1.0143x over previous
#include <cuda_runtime.h>
#include <math.h>

#define Nn 50000
#define Ee 400000
#define NBLK 196   // ceil(Nn/256)

// output packing: out[N*4], nh[N*64], nc[N*64], eh[E*32], ec[E*32]
#define OUT_OFF 0
#define NH_OFF  (Nn*4)
#define NC_OFF  (NH_OFF + Nn*64)
#define EH_OFF  (NC_OFF + Nn*64)
#define EC_OFF  (EH_OFF + Ee*32)

// ---------------- scratch ----------------
__device__ int   g_cnti[Nn];
__device__ int   g_bsum[256];
__device__ int   g_boff[256];
__device__ int   g_off[Nn+1];
__device__ int   g_cursor[Nn];
__device__ int   g_eid[Ee];
__device__ int   g_esrc[Ee];
__device__ float g_cntf[Nn];
__device__ float g_xcat[Nn*96];
__device__ float g_xh[Nn*256];
__device__ float g_as[Nn*4];
__device__ float g_ad[Nn*4];
__device__ float g_xgat[Nn*64];
__device__ float g_P[Nn*64];
__device__ float g_Q[Nn*64];
__device__ float g_elat[Ee*32];
__device__ float g_agg[Nn*32];

typedef unsigned long long u64;
__device__ __forceinline__ u64 pk2(float lo, float hi){ u64 r; asm("mov.b64 %0, {%1,%2};" : "=l"(r) : "f"(lo), "f"(hi)); return r; }
__device__ __forceinline__ u64 dup2(float v){ return pk2(v,v); }
__device__ __forceinline__ void fma2(u64 &acc, u64 a, u64 b){ asm("fma.rn.f32x2 %0, %1, %2, %0;" : "+l"(acc) : "l"(a), "l"(b)); }
__device__ __forceinline__ void up2(u64 v, float &lo, float &hi){ asm("mov.b64 {%0,%1}, %2;" : "=f"(lo), "=f"(hi) : "l"(v)); }

__device__ __forceinline__ float fsig(float x){ return __fdividef(1.f, 1.f+__expf(-x)); }
__device__ __forceinline__ float ftanhf(float x){ return __fdividef(2.f, 1.f+__expf(-2.f*x)) - 1.f; }
__device__ __forceinline__ float leaky(float x){ return x > 0.f ? x : 0.2f*x; }

// ================= CSR build =================
__global__ void k_zero_cnt(){
    int t = blockIdx.x*blockDim.x + threadIdx.x;
    if (t < Nn) g_cnti[t] = 0;
}
__global__ void k_count(const int* __restrict__ ei){
    int e = blockIdx.x*blockDim.x + threadIdx.x;
    if (e < Ee) atomicAdd(&g_cnti[ei[Ee+e]], 1);
}
__global__ void k_scan1(){
    __shared__ int s[256];
    int i = blockIdx.x*256 + threadIdx.x;
    s[threadIdx.x] = (i < Nn) ? g_cnti[i] : 0;
    __syncthreads();
    for (int o=128; o; o>>=1){
        if (threadIdx.x < o) s[threadIdx.x] += s[threadIdx.x+o];
        __syncthreads();
    }
    if (threadIdx.x == 0) g_bsum[blockIdx.x] = s[0];
}
__global__ void k_scan2(){
    __shared__ int s[256];
    int t = threadIdx.x;
    s[t] = (t < NBLK) ? g_bsum[t] : 0;
    __syncthreads();
    if (t == 0){
        int run = 0;
        for (int i=0;i<NBLK;i++){ int v=s[i]; s[i]=run; run+=v; }
    }
    __syncthreads();
    if (t < NBLK) g_boff[t] = s[t];
}
__global__ void k_scan3(){
    __shared__ int s[256];
    int t = threadIdx.x;
    int i = blockIdx.x*256 + t;
    int cnt = (i < Nn) ? g_cnti[i] : 0;
    s[t] = cnt;
    __syncthreads();
    for (int o=1; o<256; o<<=1){
        int v = (t >= o) ? s[t-o] : 0;
        __syncthreads();
        s[t] += v;
        __syncthreads();
    }
    int off = g_boff[blockIdx.x] + s[t] - cnt;
    if (i < Nn){
        g_off[i] = off;
        g_cursor[i] = off;
        g_cntf[i] = (float)cnt;
        if (i == Nn-1) g_off[Nn] = off + cnt;
    }
}
__global__ void k_bin(const int* __restrict__ ei){
    int e = blockIdx.x*blockDim.x + threadIdx.x;
    if (e >= Ee) return;
    int d = ei[Ee+e];
    int p = atomicAdd(&g_cursor[d], 1);
    g_eid[p]  = e;
    g_esrc[p] = ei[e];
}

// ---------- K1: edge LSTM v3 — swizzled staged IO + f32x2 quads ----------
// dyn smem layout (floats): [0,4096) weight quads, [4096,4352) Wih,
// [4352,4480) b, [4480, 4480+8192) per-warp tiles: warp w gets
// mH = 4480 + w*2048 (h tile, reused for eh), mC = mH+1024 (c tile -> ec)
__global__ void __launch_bounds__(128) k_edge_lstm(
        const float* __restrict__ ea,
        const float* __restrict__ h0, const float* __restrict__ c0,
        const float* __restrict__ Wih, const float* __restrict__ Whh,
        const float* __restrict__ b, float* __restrict__ outp){
    extern __shared__ float dyn[];
    float* sQf  = dyn;
    float* sWih = dyn + 4096;
    float* sb   = dyn + 4352;
    for (int i=threadIdx.x; i<4096; i+=128){
        int r = i>>5, k = i&31;
        sQf[((k>>1)*64 + (r>>1))*4 + (r&1) + 2*(k&1)] = Whh[i];
    }
    for (int i=threadIdx.x; i<256; i+=128) sWih[i] = Wih[i];
    for (int i=threadIdx.x; i<128; i+=128) sb[i] = b[i];
    __syncthreads();

    int warp = threadIdx.x>>5, lane = threadIdx.x&31;
    int e0 = (blockIdx.x*4 + warp)*32;          // 32 edges per warp (exact: 400000/32=12500)
    float* mH = dyn + 4480 + warp*2048;
    float* mC = mH + 1024;

    // stage h0, c0 tiles (coalesced loads, swizzled stores)
    {
        const float4* gh = (const float4*)(h0 + (size_t)e0*32);
        const float4* gc = (const float4*)(c0 + (size_t)e0*32);
        #pragma unroll
        for (int i=0;i<8;i++){
            int j = lane + 32*i;       // quad index in tile
            int e = j>>3, q = j&7;
            int slot = e*32 + ((q ^ (e&7))<<2);
            *(float4*)&mH[slot] = gh[j];
            *(float4*)&mC[slot] = gc[j];
        }
    }
    __syncwarp();

    // own h row -> registers (conflict-free swizzled reads)
    float h[32];
    #pragma unroll
    for (int i=0;i<8;i++){
        float4 v = *(float4*)&mH[lane*32 + ((i ^ (lane&7))<<2)];
        h[4*i]=v.x; h[4*i+1]=v.y; h[4*i+2]=v.z; h[4*i+3]=v.w;
    }
    // from here each thread touches only row `lane` of mH/mC — no cross-thread hazard
    float2 xv = ((const float2*)ea)[e0 + lane];
    const ulonglong2* sQ2 = (const ulonglong2*)sQf;

    #pragma unroll 1
    for (int j0=0;j0<32;j0+=4){
        u64 acc[4][2];   // [gate][pair]
        #pragma unroll
        for (int g=0; g<4; g++)
            #pragma unroll
            for (int p=0; p<2; p++){
                int r0 = g*32 + j0 + 2*p;
                float alo = sb[r0]   + xv.x*sWih[2*r0]   + xv.y*sWih[2*r0+1];
                float ahi = sb[r0+1] + xv.x*sWih[2*r0+2] + xv.y*sWih[2*r0+3];
                acc[g][p] = pk2(alo, ahi);
            }
        #pragma unroll
        for (int k2=0; k2<16; k2++){
            u64 xlo = dup2(h[2*k2]);
            u64 xhi = dup2(h[2*k2+1]);
            #pragma unroll
            for (int g=0; g<4; g++)
                #pragma unroll
                for (int p=0; p<2; p++){
                    ulonglong2 q = sQ2[k2*64 + g*16 + (j0>>1) + p];
                    fma2(acc[g][p], xlo, q.x);
                    fma2(acc[g][p], xhi, q.y);
                }
        }
        float gi[4], gf[4], gg[4], go[4];
        #pragma unroll
        for (int p=0; p<2; p++){
            up2(acc[0][p], gi[2*p], gi[2*p+1]);
            up2(acc[1][p], gf[2*p], gf[2*p+1]);
            up2(acc[2][p], gg[2*p], gg[2*p+1]);
            up2(acc[3][p], go[2*p], go[2*p+1]);
        }
        int slot = lane*32 + (((j0>>2) ^ (lane&7))<<2);
        float4 cv = *(float4*)&mC[slot];
        float cc[4] = {cv.x, cv.y, cv.z, cv.w};
        float h2a[4], c2a[4];
        #pragma unroll
        for (int u=0; u<4; u++){
            float c2 = fsig(gf[u])*cc[u] + fsig(gi[u])*ftanhf(gg[u]);
            float h2 = fsig(go[u])*ftanhf(c2);
            h2a[u]=h2; c2a[u]=c2;
        }
        *(float4*)&mH[slot] = make_float4(h2a[0],h2a[1],h2a[2],h2a[3]);
        *(float4*)&mC[slot] = make_float4(c2a[0],c2a[1],c2a[2],c2a[3]);
    }
    __syncwarp();
    // coalesced flush of eh/ec tiles
    {
        float4* geh = (float4*)(outp + EH_OFF + (size_t)e0*32);
        float4* gec = (float4*)(outp + EC_OFF + (size_t)e0*32);
        #pragma unroll
        for (int i=0;i<8;i++){
            int j = lane + 32*i;
            int e = j>>3, q = j&7;
            int slot = e*32 + ((q ^ (e&7))<<2);
            geh[j] = *(float4*)&mH[slot];
            gec[j] = *(float4*)&mC[slot];
        }
    }
}

// ---------- K2: node LSTM, f32x2 quad-packed ----------
__global__ void __launch_bounds__(128) k_node_lstm(
        const float* __restrict__ x, const float* __restrict__ h0,
        const float* __restrict__ c0, const float* __restrict__ Wih,
        const float* __restrict__ Whh, const float* __restrict__ b,
        float* __restrict__ outp){
    extern __shared__ float dyn[];
    float* sQf  = dyn;                  // 16384 floats
    float* sWih = dyn + 16384;          // 1280
    float* sb   = sWih + 1280;          // 256
    for (int i=threadIdx.x; i<16384; i+=128){
        int r = i>>6, k = i&63;
        sQf[((k>>1)*128 + (r>>1))*4 + (r&1) + 2*(k&1)] = Whh[i];
    }
    for (int i=threadIdx.x; i<1280; i+=128) sWih[i] = Wih[i];
    for (int i=threadIdx.x; i<256;  i+=128) sb[i] = b[i];
    __syncthreads();
    int node = blockIdx.x*128 + threadIdx.x;
    if (node >= Nn) return;

    float xr[5];
    #pragma unroll
    for (int k=0;k<5;k++) xr[k] = x[node*5+k];
    float h[64];
    {
        const float4* h0v = (const float4*)h0;
        #pragma unroll
        for (int i=0;i<16;i++){
            float4 v = h0v[node*16+i];
            h[4*i]=v.x; h[4*i+1]=v.y; h[4*i+2]=v.z; h[4*i+3]=v.w;
        }
    }
    const float4* c0v = (const float4*)c0;
    float4* outv = (float4*)outp;
    const ulonglong2* sQ2 = (const ulonglong2*)sQf;

    #pragma unroll 1
    for (int j0=0;j0<64;j0+=4){
        u64 acc[4][2];
        #pragma unroll
        for (int g=0; g<4; g++)
            #pragma unroll
            for (int p=0; p<2; p++){
                int r0 = g*64 + j0 + 2*p;
                float alo = sb[r0], ahi = sb[r0+1];
                #pragma unroll
                for (int k=0;k<5;k++){
                    alo += xr[k]*sWih[r0*5+k];
                    ahi += xr[k]*sWih[(r0+1)*5+k];
                }
                acc[g][p] = pk2(alo, ahi);
            }
        #pragma unroll
        for (int k2=0; k2<32; k2++){
            u64 xlo = dup2(h[2*k2]);
            u64 xhi = dup2(h[2*k2+1]);
            #pragma unroll
            for (int g=0; g<4; g++)
                #pragma unroll
                for (int p=0; p<2; p++){
                    ulonglong2 q = sQ2[k2*128 + g*32 + (j0>>1) + p];
                    fma2(acc[g][p], xlo, q.x);
                    fma2(acc[g][p], xhi, q.y);
                }
        }
        float gi[4], gf[4], gg[4], go[4];
        #pragma unroll
        for (int p=0; p<2; p++){
            up2(acc[0][p], gi[2*p], gi[2*p+1]);
            up2(acc[1][p], gf[2*p], gf[2*p+1]);
            up2(acc[2][p], gg[2*p], gg[2*p+1]);
            up2(acc[3][p], go[2*p], go[2*p+1]);
        }
        float4 cv = c0v[node*16 + (j0>>2)];
        float cc[4] = {cv.x, cv.y, cv.z, cv.w};
        float h2a[4], c2a[4];
        #pragma unroll
        for (int u=0; u<4; u++){
            float c2 = fsig(gf[u])*cc[u] + fsig(gi[u])*ftanhf(gg[u]);
            float h2 = fsig(go[u])*ftanhf(c2);
            h2a[u]=h2; c2a[u]=c2;
        }
        float4 h2v = make_float4(h2a[0],h2a[1],h2a[2],h2a[3]);
        outv[(NH_OFF + node*64 + j0)>>2] = h2v;
        outv[(NC_OFF + node*64 + j0)>>2] = make_float4(c2a[0],c2a[1],c2a[2],c2a[3]);
        ((float4*)g_xcat)[(node*96 + j0)>>2] = h2v;
    }
}

// ---------- K3: enc gather ----------
__global__ void __launch_bounds__(256) k_enc_gather(const float* __restrict__ outp){
    int warp = threadIdx.x>>5, lane = threadIdx.x&31;
    int n = blockIdx.x*8 + warp;
    if (n >= Nn) return;
    int beg = g_off[n], end = g_off[n+1];
    float acc = 0.f;
    for (int i=beg; i<end; i++){
        int e = g_eid[i];
        acc += outp[EH_OFF + e*32 + lane];
    }
    g_xcat[n*96 + 64 + lane] = __fdividef(acc, fmaxf(g_cntf[n], 1.f));
}

// ---------- K4: GAT projection + logits, thread/node quad-packed ----------
__global__ void __launch_bounds__(128) k_gat_proj(const float* __restrict__ W,
                                                  const float* __restrict__ att_s,
                                                  const float* __restrict__ att_d){
    extern __shared__ float dyn[];
    float* sQf = dyn;            // 24576 floats: quad[(k2)*128 + jp]
    float* ss  = dyn + 24576;    // 256
    float* sd  = ss + 256;       // 256
    for (int i=threadIdx.x; i<24576; i+=128){
        int r = i/96, k = i - r*96;
        sQf[((k>>1)*128 + (r>>1))*4 + (r&1) + 2*(k&1)] = W[i];
    }
    for (int i=threadIdx.x; i<256; i+=128){ ss[i]=att_s[i]; sd[i]=att_d[i]; }
    __syncthreads();
    int n = blockIdx.x*128 + threadIdx.x;
    if (n >= Nn) return;

    float xc[96];
    {
        const float4* xv = (const float4*)(g_xcat + n*96);
        #pragma unroll
        for (int i=0;i<24;i++){
            float4 v = xv[i];
            xc[4*i]=v.x; xc[4*i+1]=v.y; xc[4*i+2]=v.z; xc[4*i+3]=v.w;
        }
    }
    const ulonglong2* sQ2 = (const ulonglong2*)sQf;
    float asa[4] = {0,0,0,0}, ada[4] = {0,0,0,0};

    #pragma unroll 1
    for (int rb=0; rb<16; rb++){
        u64 acc[8];
        #pragma unroll
        for (int p=0;p<8;p++) acc[p] = 0ull;
        #pragma unroll
        for (int k2=0; k2<48; k2++){
            u64 xlo = dup2(xc[2*k2]);
            u64 xhi = dup2(xc[2*k2+1]);
            #pragma unroll
            for (int p=0;p<8;p++){
                ulonglong2 q = sQ2[k2*128 + rb*8 + p];
                fma2(acc[p], xlo, q.x);
                fma2(acc[p], xhi, q.y);
            }
        }
        float v[16];
        #pragma unroll
        for (int p=0;p<8;p++) up2(acc[p], v[2*p], v[2*p+1]);
        int hd = rb>>2;
        #pragma unroll
        for (int u=0;u<16;u++){
            int r = rb*16 + u;
            asa[hd] += v[u]*ss[r];
            ada[hd] += v[u]*sd[r];
        }
        float4* xh4 = (float4*)(g_xh + (size_t)n*256 + rb*16);
        xh4[0] = make_float4(v[0],v[1],v[2],v[3]);
        xh4[1] = make_float4(v[4],v[5],v[6],v[7]);
        xh4[2] = make_float4(v[8],v[9],v[10],v[11]);
        xh4[3] = make_float4(v[12],v[13],v[14],v[15]);
    }
    *(float4*)&g_as[n*4] = make_float4(asa[0],asa[1],asa[2],asa[3]);
    *(float4*)&g_ad[n*4] = make_float4(ada[0],ada[1],ada[2],ada[3]);
}

// ---------- K5: fused GAT softmax+aggregate (warp/dst) ----------
__global__ void __launch_bounds__(256) k_gat_fused(const float* __restrict__ bias){
    __shared__ float sbias[64];
    if (threadIdx.x < 64) sbias[threadIdx.x] = bias[threadIdx.x];
    __syncthreads();
    int warp = threadIdx.x>>5, lane = threadIdx.x&31;
    int n = blockIdx.x*8 + warp;
    if (n >= Nn) return;
    float4 adv = *(const float4*)&g_ad[n*4];
    float4 asv = *(const float4*)&g_as[n*4];
    float m[4];
    m[0]=leaky(asv.x+adv.x); m[1]=leaky(asv.y+adv.y);
    m[2]=leaky(asv.z+adv.z); m[3]=leaky(asv.w+adv.w);
    float self[4] = {m[0],m[1],m[2],m[3]};
    int beg = g_off[n], end = g_off[n+1];
    for (int i=beg+lane; i<end; i+=32){
        int s = g_esrc[i];
        float4 av = *(const float4*)&g_as[s*4];
        m[0]=fmaxf(m[0], leaky(av.x+adv.x));
        m[1]=fmaxf(m[1], leaky(av.y+adv.y));
        m[2]=fmaxf(m[2], leaky(av.z+adv.z));
        m[3]=fmaxf(m[3], leaky(av.w+adv.w));
    }
    #pragma unroll
    for (int off=16; off; off>>=1)
        #pragma unroll
        for (int h=0;h<4;h++) m[h] = fmaxf(m[h], __shfl_xor_sync(0xffffffff, m[h], off));
    float den[4], accA[4], accB[4];
    const float* xn = &g_xh[(size_t)n*256];
    #pragma unroll
    for (int h=0;h<4;h++){
        float w = __expf(self[h] - m[h]);
        den[h] = w;
        accA[h] = w * xn[h*64 + lane];
        accB[h] = w * xn[h*64 + 32 + lane];
    }
    for (int i=beg; i<end; i++){
        int s = g_esrc[i];
        float4 av = *(const float4*)&g_as[s*4];
        float w0 = __expf(leaky(av.x+adv.x) - m[0]);
        float w1 = __expf(leaky(av.y+adv.y) - m[1]);
        float w2 = __expf(leaky(av.z+adv.z) - m[2]);
        float w3 = __expf(leaky(av.w+adv.w) - m[3]);
        den[0]+=w0; den[1]+=w1; den[2]+=w2; den[3]+=w3;
        const float* xs = &g_xh[(size_t)s*256];
        accA[0] += w0*xs[lane];       accB[0] += w0*xs[32+lane];
        accA[1] += w1*xs[64+lane];    accB[1] += w1*xs[96+lane];
        accA[2] += w2*xs[128+lane];   accB[2] += w2*xs[160+lane];
        accA[3] += w3*xs[192+lane];   accB[3] += w3*xs[224+lane];
    }
    float rA = 0.f, rB = 0.f;
    #pragma unroll
    for (int h=0;h<4;h++){
        float inv = __fdividef(1.f, den[h]);
        rA += accA[h]*inv;
        rB += accB[h]*inv;
    }
    g_xgat[n*64 + lane]      = rA*0.25f + sbias[lane];
    g_xgat[n*64 + 32 + lane] = rB*0.25f + sbias[32 + lane];
}

// ---------- K6: P/Q, thread/node quad-packed ----------
__global__ void __launch_bounds__(256) k_pq(const float* __restrict__ W1, const float* __restrict__ b1){
    __shared__ float sQf[8192];
    __shared__ float sb1[64];
    for (int i=threadIdx.x; i<8192; i+=256){
        int R = i>>6, k = i&63;
        float v = (R < 64) ? W1[R*130 + k] : W1[(R-64)*130 + 64 + k];
        sQf[((k>>1)*64 + (R>>1))*4 + (R&1) + 2*(k&1)] = v;
    }
    for (int i=threadIdx.x; i<64; i+=256) sb1[i]=b1[i];
    __syncthreads();
    int n = blockIdx.x*256 + threadIdx.x;
    if (n >= Nn) return;

    float xg[64];
    {
        const float4* xv = (const float4*)(g_xgat + n*64);
        #pragma unroll
        for (int i=0;i<16;i++){
            float4 v = xv[i];
            xg[4*i]=v.x; xg[4*i+1]=v.y; xg[4*i+2]=v.z; xg[4*i+3]=v.w;
        }
    }
    const ulonglong2* sQ2 = (const ulonglong2*)sQf;
    #pragma unroll 1
    for (int rb=0; rb<8; rb++){
        u64 acc[8];
        #pragma unroll
        for (int p=0;p<8;p++){
            int r = rb*16 + 2*p;
            acc[p] = (rb < 4) ? pk2(sb1[r], sb1[r+1]) : 0ull;
        }
        #pragma unroll
        for (int k2=0; k2<32; k2++){
            u64 xlo = dup2(xg[2*k2]);
            u64 xhi = dup2(xg[2*k2+1]);
            #pragma unroll
            for (int p=0;p<8;p++){
                ulonglong2 q = sQ2[k2*64 + rb*8 + p];
                fma2(acc[p], xlo, q.x);
                fma2(acc[p], xhi, q.y);
            }
        }
        float v[16];
        #pragma unroll
        for (int p=0;p<8;p++) up2(acc[p], v[2*p], v[2*p+1]);
        float* dst = (rb < 4) ? (g_P + n*64 + rb*16) : (g_Q + n*64 + (rb-4)*16);
        float4* d4 = (float4*)dst;
        d4[0] = make_float4(v[0],v[1],v[2],v[3]);
        d4[1] = make_float4(v[4],v[5],v[6],v[7]);
        d4[2] = make_float4(v[8],v[9],v[10],v[11]);
        d4[3] = make_float4(v[12],v[13],v[14],v[15]);
    }
}

// ---------- K7: edge MLP, warp per 16 edges, f32x2 tiled layer-2 ----------
__global__ void __launch_bounds__(256) k_edge_mlp(
        const int* __restrict__ ei, const float* __restrict__ ea,
        const float* __restrict__ W1, const float* __restrict__ W2,
        const float* __restrict__ b2){
    __shared__ float sW2dq[32*33*4];
    __shared__ float sw128[64], sw129[64], sb2[32];
    extern __shared__ float sHf[];
    for (int i=threadIdx.x; i<2048; i+=256){
        int l = i>>6, j = i&63;
        float v = W2[l*64+j];
        int base = (l*33 + (j>>1))*4 + 2*(j&1);
        sW2dq[base] = v; sW2dq[base+1] = v;
    }
    for (int i=threadIdx.x; i<64; i+=256){
        sw128[i]=W1[i*130+128]; sw129[i]=W1[i*130+129];
    }
    if (threadIdx.x < 32) sb2[threadIdx.x]=b2[threadIdx.x];
    __syncthreads();
    int warp = threadIdx.x>>5, lane = threadIdx.x&31;
    int base_e = (blockIdx.x*8 + warp)*16;
    if (base_e >= Ee) return;

    float* myH = sHf + warp*1024;
    for (int el=0; el<16; el++){
        int e = base_e + el;
        int s = ei[e], d = ei[Ee+e];
        float2 ev = ((const float2*)ea)[e];
        float h0 = fmaxf(g_P[s*64+lane]    + g_Q[d*64+lane]    + ev.x*sw128[lane]    + ev.y*sw129[lane],    0.f);
        float h1 = fmaxf(g_P[s*64+32+lane] + g_Q[d*64+32+lane] + ev.x*sw128[32+lane] + ev.y*sw129[32+lane], 0.f);
        int ep = el>>1, c = el&1;
        int j = lane;
        myH[(ep*32 + (j>>1))*4 + 2*(j&1) + c] = h0;
        j = lane + 32;
        myH[(ep*32 + (j>>1))*4 + 2*(j&1) + c] = h1;
    }
    __syncwarp();
    u64 acc[8];
    #pragma unroll
    for (int ep=0;ep<8;ep++) acc[ep] = dup2(sb2[lane]);
    const ulonglong2* sW2q = (const ulonglong2*)sW2dq;
    const ulonglong2* sH2 = (const ulonglong2*)myH;
    #pragma unroll 4
    for (int j2=0; j2<32; j2++){
        ulonglong2 qw = sW2q[lane*33 + j2];
        #pragma unroll
        for (int ep=0;ep<8;ep++){
            ulonglong2 xq = sH2[ep*32 + j2];
            fma2(acc[ep], xq.x, qw.x);
            fma2(acc[ep], xq.y, qw.y);
        }
    }
    #pragma unroll
    for (int ep=0;ep<8;ep++){
        float o0, o1;
        up2(acc[ep], o0, o1);
        g_elat[(base_e + 2*ep)*32 + lane]   = o0;
        g_elat[(base_e + 2*ep+1)*32 + lane] = o1;
    }
}

// ---------- K8: agg gather ----------
__global__ void __launch_bounds__(256) k_agg_gather(){
    int warp = threadIdx.x>>5, lane = threadIdx.x&31;
    int n = blockIdx.x*8 + warp;
    if (n >= Nn) return;
    int beg = g_off[n], end = g_off[n+1];
    float acc = 0.f;
    for (int i=beg; i<end; i++){
        int e = g_eid[i];
        acc += g_elat[e*32 + lane];
    }
    g_agg[n*32 + lane] = __fdividef(acc, fmaxf(g_cntf[n], 1.f));
}

// ---------- K9: node MLP ----------
__global__ void __launch_bounds__(128) k_node_mlp(
        const float* __restrict__ W1, const float* __restrict__ b1,
        const float* __restrict__ W2, const float* __restrict__ b2,
        float* __restrict__ outp){
    __shared__ float sQf[6144];
    __shared__ float sW2[256];
    __shared__ float sb1[64];
    for (int i=threadIdx.x; i<6144; i+=128){
        int r = i/96, k = i - r*96;
        sQf[((k>>1)*32 + (r>>1))*4 + (r&1) + 2*(k&1)] = W1[i];
    }
    for (int i=threadIdx.x; i<256; i+=128) sW2[i]=W2[i];
    for (int i=threadIdx.x; i<64;  i+=128) sb1[i]=b1[i];
    __syncthreads();
    int n = blockIdx.x*128 + threadIdx.x;
    if (n >= Nn) return;

    float xc[96];
    {
        const float4* xv = (const float4*)(g_xgat + n*64);
        #pragma unroll
        for (int i=0;i<16;i++){
            float4 v = xv[i];
            xc[4*i]=v.x; xc[4*i+1]=v.y; xc[4*i+2]=v.z; xc[4*i+3]=v.w;
        }
        const float4* av = (const float4*)(g_agg + n*32);
        #pragma unroll
        for (int i=0;i<8;i++){
            float4 v = av[i];
            xc[64+4*i]=v.x; xc[64+4*i+1]=v.y; xc[64+4*i+2]=v.z; xc[64+4*i+3]=v.w;
        }
    }
    const ulonglong2* sQ2 = (const ulonglong2*)sQf;
    float p[4] = {0,0,0,0};
    #pragma unroll 1
    for (int rb=0; rb<4; rb++){
        u64 acc[8];
        #pragma unroll
        for (int q=0;q<8;q++){
            int r = rb*16 + 2*q;
            acc[q] = pk2(sb1[r], sb1[r+1]);
        }
        #pragma unroll
        for (int k2=0; k2<48; k2++){
            u64 xlo = dup2(xc[2*k2]);
            u64 xhi = dup2(xc[2*k2+1]);
            #pragma unroll
            for (int q=0;q<8;q++){
                ulonglong2 w = sQ2[k2*32 + rb*8 + q];
                fma2(acc[q], xlo, w.x);
                fma2(acc[q], xhi, w.y);
            }
        }
        #pragma unroll
        for (int q=0;q<8;q++){
            float vlo, vhi;
            up2(acc[q], vlo, vhi);
            int r = rb*16 + 2*q;
            vlo = fmaxf(vlo, 0.f); vhi = fmaxf(vhi, 0.f);
            #pragma unroll
            for (int o=0;o<4;o++)
                p[o] += vlo*sW2[o*64 + r] + vhi*sW2[o*64 + r + 1];
        }
    }
    *(float4*)&outp[OUT_OFF + n*4] = make_float4(p[0]+b2[0], p[1]+b2[1], p[2]+b2[2], p[3]+b2[3]);
}

extern "C" void kernel_launch(void* const* d_in, const int* in_sizes, int n_in,
                              void* d_out, int out_size){
    (void)in_sizes; (void)n_in; (void)out_size;
    const float* x    = (const float*)d_in[0];
    const int*   ei   = (const int*)  d_in[1];
    const float* ea   = (const float*)d_in[2];
    const float* hnh  = (const float*)d_in[3];
    const float* hnc  = (const float*)d_in[4];
    const float* heh  = (const float*)d_in[5];
    const float* hec  = (const float*)d_in[6];
    const float* nWih = (const float*)d_in[7];
    const float* nWhh = (const float*)d_in[8];
    const float* nb   = (const float*)d_in[9];
    const float* eWih = (const float*)d_in[10];
    const float* eWhh = (const float*)d_in[11];
    const float* eb   = (const float*)d_in[12];
    const float* gatW = (const float*)d_in[13];
    const float* attS = (const float*)d_in[14];
    const float* attD = (const float*)d_in[15];
    const float* gatB = (const float*)d_in[16];
    const float* emW1 = (const float*)d_in[17];
    const float* emb1 = (const float*)d_in[18];
    const float* emW2 = (const float*)d_in[19];
    const float* emb2 = (const float*)d_in[20];
    const float* nmW1 = (const float*)d_in[21];
    const float* nmb1 = (const float*)d_in[22];
    const float* nmW2 = (const float*)d_in[23];
    const float* nmb2 = (const float*)d_in[24];
    float* out = (float*)d_out;

    static const int elstm_smem = (4096 + 256 + 128 + 8192)*4;   // 50688
    static const int nlstm_smem = (16384 + 1280 + 256)*4;        // 71680
    static const int gproj_smem = (24576 + 512)*4;               // 100352
    static const int emlp_smem  = 8192*4;                        // 32768
    cudaFuncSetAttribute(k_edge_lstm, cudaFuncAttributeMaxDynamicSharedMemorySize, elstm_smem);
    cudaFuncSetAttribute(k_node_lstm, cudaFuncAttributeMaxDynamicSharedMemorySize, nlstm_smem);
    cudaFuncSetAttribute(k_gat_proj,  cudaFuncAttributeMaxDynamicSharedMemorySize, gproj_smem);
    cudaFuncSetAttribute(k_edge_mlp,  cudaFuncAttributeMaxDynamicSharedMemorySize, emlp_smem);

    // CSR + encoders (edge_lstm kept at launch index 4 for ncu capture)
    k_zero_cnt<<<NBLK, 256>>>();
    k_count<<<(Ee+255)/256, 256>>>(ei);
    k_scan1<<<NBLK, 256>>>();
    k_edge_lstm<<<Ee/128, 128, elstm_smem>>>(ea, heh, hec, eWih, eWhh, eb, out);
    k_scan2<<<1, 256>>>();
    k_scan3<<<NBLK, 256>>>();
    k_bin<<<(Ee+255)/256, 256>>>(ei);
    k_node_lstm<<<(Nn+127)/128, 128, nlstm_smem>>>(x, hnh, hnc, nWih, nWhh, nb, out);
    k_enc_gather<<<(Nn+7)/8, 256>>>(out);

    // GAT
    k_gat_proj<<<(Nn+127)/128, 128, gproj_smem>>>(gatW, attS, attD);
    k_gat_fused<<<(Nn+7)/8, 256>>>(gatB);

    // GraphNetworkBlock
    k_pq<<<(Nn+255)/256, 256>>>(emW1, emb1);
    k_edge_mlp<<<(Ee+127)/128, 256, emlp_smem>>>(ei, ea, emW1, emW2, emb2);
    k_agg_gather<<<(Nn+7)/8, 256>>>();
    k_node_mlp<<<(Nn+127)/128, 128>>>(nmW1, nmb1, nmW2, nmb2, out);
}

// round 6
// speedup vs baseline: 2.4599x; 1.0903x over previous
#include <cuda_runtime.h>
#include <math.h>

#define Nn 50000
#define Ee 400000
#define NBLK 196   // ceil(Nn/256)

// output packing: out[N*4], nh[N*64], nc[N*64], eh[E*32], ec[E*32]
#define OUT_OFF 0
#define NH_OFF  (Nn*4)
#define NC_OFF  (NH_OFF + Nn*64)
#define EH_OFF  (NC_OFF + Nn*64)
#define EC_OFF  (EH_OFF + Ee*32)

// ---------------- scratch ----------------
__device__ int   g_cnti[Nn];
__device__ int   g_bsum[256];
__device__ int   g_boff[256];
__device__ int   g_off[Nn+1];
__device__ int   g_cursor[Nn];
__device__ int   g_eid[Ee];
__device__ int   g_esrc[Ee];
__device__ float g_cntf[Nn];
__device__ float g_xcat[Nn*96];
__device__ float g_xh[Nn*256];
__device__ float g_as[Nn*4];
__device__ float g_ad[Nn*4];
__device__ float g_xgat[Nn*64];
__device__ float g_P[Nn*64];
__device__ float g_Q[Nn*64];
__device__ float g_elat[Ee*32];
__device__ float g_agg[Nn*32];

typedef unsigned long long u64;
__device__ __forceinline__ u64 pk2(float lo, float hi){ u64 r; asm("mov.b64 %0, {%1,%2};" : "=l"(r) : "f"(lo), "f"(hi)); return r; }
__device__ __forceinline__ u64 dup2(float v){ return pk2(v,v); }
__device__ __forceinline__ void fma2(u64 &acc, u64 a, u64 b){ asm("fma.rn.f32x2 %0, %1, %2, %0;" : "+l"(acc) : "l"(a), "l"(b)); }
__device__ __forceinline__ void up2(u64 v, float &lo, float &hi){ asm("mov.b64 {%0,%1}, %2;" : "=f"(lo), "=f"(hi) : "l"(v)); }

__device__ __forceinline__ float tanha(float x){ float r; asm("tanh.approx.f32 %0, %1;" : "=f"(r) : "f"(x)); return r; }
__device__ __forceinline__ float fsig(float x){ return fmaf(0.5f, tanha(0.5f*x), 0.5f); }
__device__ __forceinline__ float leaky(float x){ return x > 0.f ? x : 0.2f*x; }

// ================= CSR build =================
__global__ void k_zero_cnt(){
    int t = blockIdx.x*blockDim.x + threadIdx.x;
    if (t < Nn) g_cnti[t] = 0;
}
__global__ void k_count(const int* __restrict__ ei){
    int e = blockIdx.x*blockDim.x + threadIdx.x;
    if (e < Ee) atomicAdd(&g_cnti[ei[Ee+e]], 1);
}
__global__ void k_scan1(){
    __shared__ int s[256];
    int i = blockIdx.x*256 + threadIdx.x;
    s[threadIdx.x] = (i < Nn) ? g_cnti[i] : 0;
    __syncthreads();
    for (int o=128; o; o>>=1){
        if (threadIdx.x < o) s[threadIdx.x] += s[threadIdx.x+o];
        __syncthreads();
    }
    if (threadIdx.x == 0) g_bsum[blockIdx.x] = s[0];
}
__global__ void k_scan2(){
    __shared__ int s[256];
    int t = threadIdx.x;
    s[t] = (t < NBLK) ? g_bsum[t] : 0;
    __syncthreads();
    if (t == 0){
        int run = 0;
        for (int i=0;i<NBLK;i++){ int v=s[i]; s[i]=run; run+=v; }
    }
    __syncthreads();
    if (t < NBLK) g_boff[t] = s[t];
}
__global__ void k_scan3(){
    __shared__ int s[256];
    int t = threadIdx.x;
    int i = blockIdx.x*256 + t;
    int cnt = (i < Nn) ? g_cnti[i] : 0;
    s[t] = cnt;
    __syncthreads();
    for (int o=1; o<256; o<<=1){
        int v = (t >= o) ? s[t-o] : 0;
        __syncthreads();
        s[t] += v;
        __syncthreads();
    }
    int off = g_boff[blockIdx.x] + s[t] - cnt;
    if (i < Nn){
        g_off[i] = off;
        g_cursor[i] = off;
        g_cntf[i] = (float)cnt;
        if (i == Nn-1) g_off[Nn] = off + cnt;
    }
}
__global__ void k_bin(const int* __restrict__ ei){
    int e = blockIdx.x*blockDim.x + threadIdx.x;
    if (e >= Ee) return;
    int d = ei[Ee+e];
    int p = atomicAdd(&g_cursor[d], 1);
    g_eid[p]  = e;
    g_esrc[p] = ei[e];
}

// ---------- K1: edge LSTM v4 — 2 edges/thread, swizzled staging, f32x2 ----
// dyn smem (floats): [0,4096) W quads, [4096,4352) Wih, [4352,4480) b,
// tiles: warp w: mH = 4480 + w*4096 (64 edges x 32), mC = mH + 2048
__global__ void __launch_bounds__(128) k_edge_lstm(
        const float* __restrict__ ea,
        const float* __restrict__ h0, const float* __restrict__ c0,
        const float* __restrict__ Wih, const float* __restrict__ Whh,
        const float* __restrict__ b, float* __restrict__ outp){
    extern __shared__ float dyn[];
    float* sQf  = dyn;
    float* sWih = dyn + 4096;
    float* sb   = dyn + 4352;
    for (int i=threadIdx.x; i<4096; i+=128){
        int r = i>>5, k = i&31;
        sQf[((k>>1)*64 + (r>>1))*4 + (r&1) + 2*(k&1)] = Whh[i];
    }
    for (int i=threadIdx.x; i<256; i+=128) sWih[i] = Wih[i];
    for (int i=threadIdx.x; i<128; i+=128) sb[i] = b[i];
    __syncthreads();

    int warp = threadIdx.x>>5, lane = threadIdx.x&31;
    int e0 = (blockIdx.x*4 + warp)*64;
    if (e0 >= Ee) return;                 // tail warps idle (Ee%64==0)
    float* mH = dyn + 4480 + warp*4096;
    float* mC = mH + 2048;

    // stage h0, c0 tiles (coalesced loads, swizzled stores)
    {
        const float4* gh = (const float4*)(h0 + (size_t)e0*32);
        const float4* gc = (const float4*)(c0 + (size_t)e0*32);
        #pragma unroll
        for (int i=0;i<16;i++){
            int j = lane + 32*i;
            int e = j>>3, q = j&7;
            int slot = e*32 + ((q ^ (e&7))<<2);
            *(float4*)&mH[slot] = gh[j];
            *(float4*)&mC[slot] = gc[j];
        }
    }
    __syncwarp();

    // own 2 rows -> registers
    float h[2][32];
    #pragma unroll
    for (int u=0;u<2;u++){
        int row = lane + 32*u;
        #pragma unroll
        for (int i=0;i<8;i++){
            float4 v = *(float4*)&mH[row*32 + ((i ^ (row&7))<<2)];
            h[u][4*i]=v.x; h[u][4*i+1]=v.y; h[u][4*i+2]=v.z; h[u][4*i+3]=v.w;
        }
    }
    float2 xv[2];
    xv[0] = ((const float2*)ea)[e0 + lane];
    xv[1] = ((const float2*)ea)[e0 + 32 + lane];
    const ulonglong2* sQ2 = (const ulonglong2*)sQf;

    #pragma unroll 1
    for (int j0=0;j0<32;j0+=4){
        u64 acc[2][4][2];   // [edge][gate][pair]
        #pragma unroll
        for (int u=0;u<2;u++)
            #pragma unroll
            for (int g=0; g<4; g++)
                #pragma unroll
                for (int p=0; p<2; p++){
                    int r0 = g*32 + j0 + 2*p;
                    float alo = sb[r0]   + xv[u].x*sWih[2*r0]   + xv[u].y*sWih[2*r0+1];
                    float ahi = sb[r0+1] + xv[u].x*sWih[2*r0+2] + xv[u].y*sWih[2*r0+3];
                    acc[u][g][p] = pk2(alo, ahi);
                }
        #pragma unroll
        for (int k2=0; k2<16; k2++){
            u64 x0lo = dup2(h[0][2*k2]), x0hi = dup2(h[0][2*k2+1]);
            u64 x1lo = dup2(h[1][2*k2]), x1hi = dup2(h[1][2*k2+1]);
            #pragma unroll
            for (int g=0; g<4; g++)
                #pragma unroll
                for (int p=0; p<2; p++){
                    ulonglong2 q = sQ2[k2*64 + g*16 + (j0>>1) + p];
                    fma2(acc[0][g][p], x0lo, q.x);
                    fma2(acc[0][g][p], x0hi, q.y);
                    fma2(acc[1][g][p], x1lo, q.x);
                    fma2(acc[1][g][p], x1hi, q.y);
                }
        }
        #pragma unroll
        for (int u=0;u<2;u++){
            float gi[4], gf[4], gg[4], go[4];
            #pragma unroll
            for (int p=0; p<2; p++){
                up2(acc[u][0][p], gi[2*p], gi[2*p+1]);
                up2(acc[u][1][p], gf[2*p], gf[2*p+1]);
                up2(acc[u][2][p], gg[2*p], gg[2*p+1]);
                up2(acc[u][3][p], go[2*p], go[2*p+1]);
            }
            int row = lane + 32*u;
            int slot = row*32 + (((j0>>2) ^ (row&7))<<2);
            float4 cv = *(float4*)&mC[slot];
            float cc[4] = {cv.x, cv.y, cv.z, cv.w};
            float h2a[4], c2a[4];
            #pragma unroll
            for (int t=0; t<4; t++){
                float c2 = fsig(gf[t])*cc[t] + fsig(gi[t])*tanha(gg[t]);
                float h2 = fsig(go[t])*tanha(c2);
                h2a[t]=h2; c2a[t]=c2;
            }
            *(float4*)&mH[slot] = make_float4(h2a[0],h2a[1],h2a[2],h2a[3]);
            *(float4*)&mC[slot] = make_float4(c2a[0],c2a[1],c2a[2],c2a[3]);
        }
    }
    __syncwarp();
    // coalesced flush
    {
        float4* geh = (float4*)(outp + EH_OFF + (size_t)e0*32);
        float4* gec = (float4*)(outp + EC_OFF + (size_t)e0*32);
        #pragma unroll
        for (int i=0;i<16;i++){
            int j = lane + 32*i;
            int e = j>>3, q = j&7;
            int slot = e*32 + ((q ^ (e&7))<<2);
            geh[j] = *(float4*)&mH[slot];
            gec[j] = *(float4*)&mC[slot];
        }
    }
}

// ---------- K2: node LSTM, f32x2 quad-packed + tanh.approx ----------
__global__ void __launch_bounds__(128) k_node_lstm(
        const float* __restrict__ x, const float* __restrict__ h0,
        const float* __restrict__ c0, const float* __restrict__ Wih,
        const float* __restrict__ Whh, const float* __restrict__ b,
        float* __restrict__ outp){
    extern __shared__ float dyn[];
    float* sQf  = dyn;                  // 16384 floats
    float* sWih = dyn + 16384;          // 1280
    float* sb   = sWih + 1280;          // 256
    for (int i=threadIdx.x; i<16384; i+=128){
        int r = i>>6, k = i&63;
        sQf[((k>>1)*128 + (r>>1))*4 + (r&1) + 2*(k&1)] = Whh[i];
    }
    for (int i=threadIdx.x; i<1280; i+=128) sWih[i] = Wih[i];
    for (int i=threadIdx.x; i<256;  i+=128) sb[i] = b[i];
    __syncthreads();
    int node = blockIdx.x*128 + threadIdx.x;
    if (node >= Nn) return;

    float xr[5];
    #pragma unroll
    for (int k=0;k<5;k++) xr[k] = x[node*5+k];
    float h[64];
    {
        const float4* h0v = (const float4*)h0;
        #pragma unroll
        for (int i=0;i<16;i++){
            float4 v = h0v[node*16+i];
            h[4*i]=v.x; h[4*i+1]=v.y; h[4*i+2]=v.z; h[4*i+3]=v.w;
        }
    }
    const float4* c0v = (const float4*)c0;
    float4* outv = (float4*)outp;
    const ulonglong2* sQ2 = (const ulonglong2*)sQf;

    #pragma unroll 1
    for (int j0=0;j0<64;j0+=4){
        u64 acc[4][2];
        #pragma unroll
        for (int g=0; g<4; g++)
            #pragma unroll
            for (int p=0; p<2; p++){
                int r0 = g*64 + j0 + 2*p;
                float alo = sb[r0], ahi = sb[r0+1];
                #pragma unroll
                for (int k=0;k<5;k++){
                    alo += xr[k]*sWih[r0*5+k];
                    ahi += xr[k]*sWih[(r0+1)*5+k];
                }
                acc[g][p] = pk2(alo, ahi);
            }
        #pragma unroll
        for (int k2=0; k2<32; k2++){
            u64 xlo = dup2(h[2*k2]);
            u64 xhi = dup2(h[2*k2+1]);
            #pragma unroll
            for (int g=0; g<4; g++)
                #pragma unroll
                for (int p=0; p<2; p++){
                    ulonglong2 q = sQ2[k2*128 + g*32 + (j0>>1) + p];
                    fma2(acc[g][p], xlo, q.x);
                    fma2(acc[g][p], xhi, q.y);
                }
        }
        float gi[4], gf[4], gg[4], go[4];
        #pragma unroll
        for (int p=0; p<2; p++){
            up2(acc[0][p], gi[2*p], gi[2*p+1]);
            up2(acc[1][p], gf[2*p], gf[2*p+1]);
            up2(acc[2][p], gg[2*p], gg[2*p+1]);
            up2(acc[3][p], go[2*p], go[2*p+1]);
        }
        float4 cv = c0v[node*16 + (j0>>2)];
        float cc[4] = {cv.x, cv.y, cv.z, cv.w};
        float h2a[4], c2a[4];
        #pragma unroll
        for (int u=0; u<4; u++){
            float c2 = fsig(gf[u])*cc[u] + fsig(gi[u])*tanha(gg[u]);
            float h2 = fsig(go[u])*tanha(c2);
            h2a[u]=h2; c2a[u]=c2;
        }
        float4 h2v = make_float4(h2a[0],h2a[1],h2a[2],h2a[3]);
        outv[(NH_OFF + node*64 + j0)>>2] = h2v;
        outv[(NC_OFF + node*64 + j0)>>2] = make_float4(c2a[0],c2a[1],c2a[2],c2a[3]);
        ((float4*)g_xcat)[(node*96 + j0)>>2] = h2v;
    }
}

// ---------- K3: enc gather ----------
__global__ void __launch_bounds__(256) k_enc_gather(const float* __restrict__ outp){
    int warp = threadIdx.x>>5, lane = threadIdx.x&31;
    int n = blockIdx.x*8 + warp;
    if (n >= Nn) return;
    int beg = g_off[n], end = g_off[n+1];
    float acc = 0.f;
    for (int i=beg; i<end; i++){
        int e = g_eid[i];
        acc += outp[EH_OFF + e*32 + lane];
    }
    g_xcat[n*96 + 64 + lane] = __fdividef(acc, fmaxf(g_cntf[n], 1.f));
}

// ---------- K4: GAT projection + logits ----------
__global__ void __launch_bounds__(128) k_gat_proj(const float* __restrict__ W,
                                                  const float* __restrict__ att_s,
                                                  const float* __restrict__ att_d){
    extern __shared__ float dyn[];
    float* sQf = dyn;            // 24576 floats
    float* ss  = dyn + 24576;    // 256
    float* sd  = ss + 256;       // 256
    for (int i=threadIdx.x; i<24576; i+=128){
        int r = i/96, k = i - r*96;
        sQf[((k>>1)*128 + (r>>1))*4 + (r&1) + 2*(k&1)] = W[i];
    }
    for (int i=threadIdx.x; i<256; i+=128){ ss[i]=att_s[i]; sd[i]=att_d[i]; }
    __syncthreads();
    int n = blockIdx.x*128 + threadIdx.x;
    if (n >= Nn) return;

    float xc[96];
    {
        const float4* xv = (const float4*)(g_xcat + n*96);
        #pragma unroll
        for (int i=0;i<24;i++){
            float4 v = xv[i];
            xc[4*i]=v.x; xc[4*i+1]=v.y; xc[4*i+2]=v.z; xc[4*i+3]=v.w;
        }
    }
    const ulonglong2* sQ2 = (const ulonglong2*)sQf;
    float asa[4] = {0,0,0,0}, ada[4] = {0,0,0,0};

    #pragma unroll 1
    for (int rb=0; rb<16; rb++){
        u64 acc[8];
        #pragma unroll
        for (int p=0;p<8;p++) acc[p] = 0ull;
        #pragma unroll
        for (int k2=0; k2<48; k2++){
            u64 xlo = dup2(xc[2*k2]);
            u64 xhi = dup2(xc[2*k2+1]);
            #pragma unroll
            for (int p=0;p<8;p++){
                ulonglong2 q = sQ2[k2*128 + rb*8 + p];
                fma2(acc[p], xlo, q.x);
                fma2(acc[p], xhi, q.y);
            }
        }
        float v[16];
        #pragma unroll
        for (int p=0;p<8;p++) up2(acc[p], v[2*p], v[2*p+1]);
        int hd = rb>>2;
        #pragma unroll
        for (int u=0;u<16;u++){
            int r = rb*16 + u;
            asa[hd] += v[u]*ss[r];
            ada[hd] += v[u]*sd[r];
        }
        float4* xh4 = (float4*)(g_xh + (size_t)n*256 + rb*16);
        xh4[0] = make_float4(v[0],v[1],v[2],v[3]);
        xh4[1] = make_float4(v[4],v[5],v[6],v[7]);
        xh4[2] = make_float4(v[8],v[9],v[10],v[11]);
        xh4[3] = make_float4(v[12],v[13],v[14],v[15]);
    }
    *(float4*)&g_as[n*4] = make_float4(asa[0],asa[1],asa[2],asa[3]);
    *(float4*)&g_ad[n*4] = make_float4(ada[0],ada[1],ada[2],ada[3]);
}

// ---------- K5: fused GAT softmax+aggregate (warp/dst) ----------
__global__ void __launch_bounds__(256) k_gat_fused(const float* __restrict__ bias){
    __shared__ float sbias[64];
    if (threadIdx.x < 64) sbias[threadIdx.x] = bias[threadIdx.x];
    __syncthreads();
    int warp = threadIdx.x>>5, lane = threadIdx.x&31;
    int n = blockIdx.x*8 + warp;
    if (n >= Nn) return;
    float4 adv = *(const float4*)&g_ad[n*4];
    float4 asv = *(const float4*)&g_as[n*4];
    float m[4];
    m[0]=leaky(asv.x+adv.x); m[1]=leaky(asv.y+adv.y);
    m[2]=leaky(asv.z+adv.z); m[3]=leaky(asv.w+adv.w);
    float self[4] = {m[0],m[1],m[2],m[3]};
    int beg = g_off[n], end = g_off[n+1];
    for (int i=beg+lane; i<end; i+=32){
        int s = g_esrc[i];
        float4 av = *(const float4*)&g_as[s*4];
        m[0]=fmaxf(m[0], leaky(av.x+adv.x));
        m[1]=fmaxf(m[1], leaky(av.y+adv.y));
        m[2]=fmaxf(m[2], leaky(av.z+adv.z));
        m[3]=fmaxf(m[3], leaky(av.w+adv.w));
    }
    #pragma unroll
    for (int off=16; off; off>>=1)
        #pragma unroll
        for (int h=0;h<4;h++) m[h] = fmaxf(m[h], __shfl_xor_sync(0xffffffff, m[h], off));
    float den[4], accA[4], accB[4];
    const float* xn = &g_xh[(size_t)n*256];
    #pragma unroll
    for (int h=0;h<4;h++){
        float w = __expf(self[h] - m[h]);
        den[h] = w;
        accA[h] = w * xn[h*64 + lane];
        accB[h] = w * xn[h*64 + 32 + lane];
    }
    for (int i=beg; i<end; i++){
        int s = g_esrc[i];
        float4 av = *(const float4*)&g_as[s*4];
        float w0 = __expf(leaky(av.x+adv.x) - m[0]);
        float w1 = __expf(leaky(av.y+adv.y) - m[1]);
        float w2 = __expf(leaky(av.z+adv.z) - m[2]);
        float w3 = __expf(leaky(av.w+adv.w) - m[3]);
        den[0]+=w0; den[1]+=w1; den[2]+=w2; den[3]+=w3;
        const float* xs = &g_xh[(size_t)s*256];
        accA[0] += w0*xs[lane];       accB[0] += w0*xs[32+lane];
        accA[1] += w1*xs[64+lane];    accB[1] += w1*xs[96+lane];
        accA[2] += w2*xs[128+lane];   accB[2] += w2*xs[160+lane];
        accA[3] += w3*xs[192+lane];   accB[3] += w3*xs[224+lane];
    }
    float rA = 0.f, rB = 0.f;
    #pragma unroll
    for (int h=0;h<4;h++){
        float inv = __fdividef(1.f, den[h]);
        rA += accA[h]*inv;
        rB += accB[h]*inv;
    }
    g_xgat[n*64 + lane]      = rA*0.25f + sbias[lane];
    g_xgat[n*64 + 32 + lane] = rB*0.25f + sbias[32 + lane];
}

// ---------- K6: P/Q ----------
__global__ void __launch_bounds__(256) k_pq(const float* __restrict__ W1, const float* __restrict__ b1){
    __shared__ float sQf[8192];
    __shared__ float sb1[64];
    for (int i=threadIdx.x; i<8192; i+=256){
        int R = i>>6, k = i&63;
        float v = (R < 64) ? W1[R*130 + k] : W1[(R-64)*130 + 64 + k];
        sQf[((k>>1)*64 + (R>>1))*4 + (R&1) + 2*(k&1)] = v;
    }
    for (int i=threadIdx.x; i<64; i+=256) sb1[i]=b1[i];
    __syncthreads();
    int n = blockIdx.x*256 + threadIdx.x;
    if (n >= Nn) return;

    float xg[64];
    {
        const float4* xv = (const float4*)(g_xgat + n*64);
        #pragma unroll
        for (int i=0;i<16;i++){
            float4 v = xv[i];
            xg[4*i]=v.x; xg[4*i+1]=v.y; xg[4*i+2]=v.z; xg[4*i+3]=v.w;
        }
    }
    const ulonglong2* sQ2 = (const ulonglong2*)sQf;
    #pragma unroll 1
    for (int rb=0; rb<8; rb++){
        u64 acc[8];
        #pragma unroll
        for (int p=0;p<8;p++){
            int r = rb*16 + 2*p;
            acc[p] = (rb < 4) ? pk2(sb1[r], sb1[r+1]) : 0ull;
        }
        #pragma unroll
        for (int k2=0; k2<32; k2++){
            u64 xlo = dup2(xg[2*k2]);
            u64 xhi = dup2(xg[2*k2+1]);
            #pragma unroll
            for (int p=0;p<8;p++){
                ulonglong2 q = sQ2[k2*64 + rb*8 + p];
                fma2(acc[p], xlo, q.x);
                fma2(acc[p], xhi, q.y);
            }
        }
        float v[16];
        #pragma unroll
        for (int p=0;p<8;p++) up2(acc[p], v[2*p], v[2*p+1]);
        float* dst = (rb < 4) ? (g_P + n*64 + rb*16) : (g_Q + n*64 + (rb-4)*16);
        float4* d4 = (float4*)dst;
        d4[0] = make_float4(v[0],v[1],v[2],v[3]);
        d4[1] = make_float4(v[4],v[5],v[6],v[7]);
        d4[2] = make_float4(v[8],v[9],v[10],v[11]);
        d4[3] = make_float4(v[12],v[13],v[14],v[15]);
    }
}

// ---------- K7: edge MLP, warp per 16 edges ----------
__global__ void __launch_bounds__(256) k_edge_mlp(
        const int* __restrict__ ei, const float* __restrict__ ea,
        const float* __restrict__ W1, const float* __restrict__ W2,
        const float* __restrict__ b2){
    __shared__ float sW2dq[32*33*4];
    __shared__ float sw128[64], sw129[64], sb2[32];
    extern __shared__ float sHf[];
    for (int i=threadIdx.x; i<2048; i+=256){
        int l = i>>6, j = i&63;
        float v = W2[l*64+j];
        int base = (l*33 + (j>>1))*4 + 2*(j&1);
        sW2dq[base] = v; sW2dq[base+1] = v;
    }
    for (int i=threadIdx.x; i<64; i+=256){
        sw128[i]=W1[i*130+128]; sw129[i]=W1[i*130+129];
    }
    if (threadIdx.x < 32) sb2[threadIdx.x]=b2[threadIdx.x];
    __syncthreads();
    int warp = threadIdx.x>>5, lane = threadIdx.x&31;
    int base_e = (blockIdx.x*8 + warp)*16;
    if (base_e >= Ee) return;

    float* myH = sHf + warp*1024;
    for (int el=0; el<16; el++){
        int e = base_e + el;
        int s = ei[e], d = ei[Ee+e];
        float2 ev = ((const float2*)ea)[e];
        float h0 = fmaxf(g_P[s*64+lane]    + g_Q[d*64+lane]    + ev.x*sw128[lane]    + ev.y*sw129[lane],    0.f);
        float h1 = fmaxf(g_P[s*64+32+lane] + g_Q[d*64+32+lane] + ev.x*sw128[32+lane] + ev.y*sw129[32+lane], 0.f);
        int ep = el>>1, c = el&1;
        int j = lane;
        myH[(ep*32 + (j>>1))*4 + 2*(j&1) + c] = h0;
        j = lane + 32;
        myH[(ep*32 + (j>>1))*4 + 2*(j&1) + c] = h1;
    }
    __syncwarp();
    u64 acc[8];
    #pragma unroll
    for (int ep=0;ep<8;ep++) acc[ep] = dup2(sb2[lane]);
    const ulonglong2* sW2q = (const ulonglong2*)sW2dq;
    const ulonglong2* sH2 = (const ulonglong2*)myH;
    #pragma unroll 4
    for (int j2=0; j2<32; j2++){
        ulonglong2 qw = sW2q[lane*33 + j2];
        #pragma unroll
        for (int ep=0;ep<8;ep++){
            ulonglong2 xq = sH2[ep*32 + j2];
            fma2(acc[ep], xq.x, qw.x);
            fma2(acc[ep], xq.y, qw.y);
        }
    }
    #pragma unroll
    for (int ep=0;ep<8;ep++){
        float o0, o1;
        up2(acc[ep], o0, o1);
        g_elat[(base_e + 2*ep)*32 + lane]   = o0;
        g_elat[(base_e + 2*ep+1)*32 + lane] = o1;
    }
}

// ---------- K8: agg gather ----------
__global__ void __launch_bounds__(256) k_agg_gather(){
    int warp = threadIdx.x>>5, lane = threadIdx.x&31;
    int n = blockIdx.x*8 + warp;
    if (n >= Nn) return;
    int beg = g_off[n], end = g_off[n+1];
    float acc = 0.f;
    for (int i=beg; i<end; i++){
        int e = g_eid[i];
        acc += g_elat[e*32 + lane];
    }
    g_agg[n*32 + lane] = __fdividef(acc, fmaxf(g_cntf[n], 1.f));
}

// ---------- K9: node MLP ----------
__global__ void __launch_bounds__(128) k_node_mlp(
        const float* __restrict__ W1, const float* __restrict__ b1,
        const float* __restrict__ W2, const float* __restrict__ b2,
        float* __restrict__ outp){
    __shared__ float sQf[6144];
    __shared__ float sW2[256];
    __shared__ float sb1[64];
    for (int i=threadIdx.x; i<6144; i+=128){
        int r = i/96, k = i - r*96;
        sQf[((k>>1)*32 + (r>>1))*4 + (r&1) + 2*(k&1)] = W1[i];
    }
    for (int i=threadIdx.x; i<256; i+=128) sW2[i]=W2[i];
    for (int i=threadIdx.x; i<64;  i+=128) sb1[i]=b1[i];
    __syncthreads();
    int n = blockIdx.x*128 + threadIdx.x;
    if (n >= Nn) return;

    float xc[96];
    {
        const float4* xv = (const float4*)(g_xgat + n*64);
        #pragma unroll
        for (int i=0;i<16;i++){
            float4 v = xv[i];
            xc[4*i]=v.x; xc[4*i+1]=v.y; xc[4*i+2]=v.z; xc[4*i+3]=v.w;
        }
        const float4* av = (const float4*)(g_agg + n*32);
        #pragma unroll
        for (int i=0;i<8;i++){
            float4 v = av[i];
            xc[64+4*i]=v.x; xc[64+4*i+1]=v.y; xc[64+4*i+2]=v.z; xc[64+4*i+3]=v.w;
        }
    }
    const ulonglong2* sQ2 = (const ulonglong2*)sQf;
    float p[4] = {0,0,0,0};
    #pragma unroll 1
    for (int rb=0; rb<4; rb++){
        u64 acc[8];
        #pragma unroll
        for (int q=0;q<8;q++){
            int r = rb*16 + 2*q;
            acc[q] = pk2(sb1[r], sb1[r+1]);
        }
        #pragma unroll
        for (int k2=0; k2<48; k2++){
            u64 xlo = dup2(xc[2*k2]);
            u64 xhi = dup2(xc[2*k2+1]);
            #pragma unroll
            for (int q=0;q<8;q++){
                ulonglong2 w = sQ2[k2*32 + rb*8 + q];
                fma2(acc[q], xlo, w.x);
                fma2(acc[q], xhi, w.y);
            }
        }
        #pragma unroll
        for (int q=0;q<8;q++){
            float vlo, vhi;
            up2(acc[q], vlo, vhi);
            int r = rb*16 + 2*q;
            vlo = fmaxf(vlo, 0.f); vhi = fmaxf(vhi, 0.f);
            #pragma unroll
            for (int o=0;o<4;o++)
                p[o] += vlo*sW2[o*64 + r] + vhi*sW2[o*64 + r + 1];
        }
    }
    *(float4*)&outp[OUT_OFF + n*4] = make_float4(p[0]+b2[0], p[1]+b2[1], p[2]+b2[2], p[3]+b2[3]);
}

extern "C" void kernel_launch(void* const* d_in, const int* in_sizes, int n_in,
                              void* d_out, int out_size){
    (void)in_sizes; (void)n_in; (void)out_size;
    const float* x    = (const float*)d_in[0];
    const int*   ei   = (const int*)  d_in[1];
    const float* ea   = (const float*)d_in[2];
    const float* hnh  = (const float*)d_in[3];
    const float* hnc  = (const float*)d_in[4];
    const float* heh  = (const float*)d_in[5];
    const float* hec  = (const float*)d_in[6];
    const float* nWih = (const float*)d_in[7];
    const float* nWhh = (const float*)d_in[8];
    const float* nb   = (const float*)d_in[9];
    const float* eWih = (const float*)d_in[10];
    const float* eWhh = (const float*)d_in[11];
    const float* eb   = (const float*)d_in[12];
    const float* gatW = (const float*)d_in[13];
    const float* attS = (const float*)d_in[14];
    const float* attD = (const float*)d_in[15];
    const float* gatB = (const float*)d_in[16];
    const float* emW1 = (const float*)d_in[17];
    const float* emb1 = (const float*)d_in[18];
    const float* emW2 = (const float*)d_in[19];
    const float* emb2 = (const float*)d_in[20];
    const float* nmW1 = (const float*)d_in[21];
    const float* nmb1 = (const float*)d_in[22];
    const float* nmW2 = (const float*)d_in[23];
    const float* nmb2 = (const float*)d_in[24];
    float* out = (float*)d_out;

    static const int elstm_smem = (4480 + 4*4096)*4;             // 83456
    static const int nlstm_smem = (16384 + 1280 + 256)*4;        // 71680
    static const int gproj_smem = (24576 + 512)*4;               // 100352
    static const int emlp_smem  = 8192*4;                        // 32768
    cudaFuncSetAttribute(k_edge_lstm, cudaFuncAttributeMaxDynamicSharedMemorySize, elstm_smem);
    cudaFuncSetAttribute(k_node_lstm, cudaFuncAttributeMaxDynamicSharedMemorySize, nlstm_smem);
    cudaFuncSetAttribute(k_gat_proj,  cudaFuncAttributeMaxDynamicSharedMemorySize, gproj_smem);
    cudaFuncSetAttribute(k_edge_mlp,  cudaFuncAttributeMaxDynamicSharedMemorySize, emlp_smem);

    // CSR + encoders (edge_lstm kept at launch index 4 for ncu capture)
    k_zero_cnt<<<NBLK, 256>>>();
    k_count<<<(Ee+255)/256, 256>>>(ei);
    k_scan1<<<NBLK, 256>>>();
    k_edge_lstm<<<(Ee/64 + 3)/4, 128, elstm_smem>>>(ea, heh, hec, eWih, eWhh, eb, out);
    k_scan2<<<1, 256>>>();
    k_scan3<<<NBLK, 256>>>();
    k_bin<<<(Ee+255)/256, 256>>>(ei);
    k_node_lstm<<<(Nn+127)/128, 128, nlstm_smem>>>(x, hnh, hnc, nWih, nWhh, nb, out);
    k_enc_gather<<<(Nn+7)/8, 256>>>(out);

    // GAT
    k_gat_proj<<<(Nn+127)/128, 128, gproj_smem>>>(gatW, attS, attD);
    k_gat_fused<<<(Nn+7)/8, 256>>>(gatB);

    // GraphNetworkBlock
    k_pq<<<(Nn+255)/256, 256>>>(emW1, emb1);
    k_edge_mlp<<<(Ee+127)/128, 256, emlp_smem>>>(ei, ea, emW1, emW2, emb2);
    k_agg_gather<<<(Nn+7)/8, 256>>>();
    k_node_mlp<<<(Nn+127)/128, 128>>>(nmW1, nmb1, nmW2, nmb2, out);
}